// round 13
// baseline (speedup 1.0000x reference)
#include <cuda_runtime.h>
#include <cuda_fp16.h>

#define NN 16
#define CC 64
#define HH 112
#define WW 112
#define HWHW (HH*WW)               // 12544
#define PKW (NN*16*HWHW)           // u8-packed NHWC act words
#define XHW (NN*HWHW*32)           // f16-packed x words (hi/mid/lo)

#define R_S  (10.0f/255.0f)
#define HT_S (10.0f/127.0f)
#define SC_M (1.0f/2048.0f)        // 2^-11
#define SC_L (1.0f/4194304.0f)     // 2^-22

// -------- device scratch ----------
__device__ unsigned g_act1[PKW];
__device__ unsigned g_act2[PKW];
__device__ unsigned g_act3[PKW];
__device__ unsigned g_act4[PKW];
__device__ unsigned g_idq [PKW];
__device__ unsigned g_xhi [XHW];
__device__ unsigned g_xmid[XHW];
__device__ unsigned g_xlo [XHW];
__device__ __align__(16) uint2 g_bfi[3*9*2*8*32];   // int-stage B fragments
__device__ __align__(16) uint2 g_bfh[9*4*8*32];     // stage0 f16 B fragments
__device__ float    g_dsq [CC*CC];
__device__ float    g_wsc [4*CC];
__device__ float    g_A   [4*CC];
__device__ float    g_B   [4*CC];
__device__ float    g_bninv4 [CC];
__device__ float    g_bnbias4[CC];

// ================= helpers =================
__device__ __forceinline__ unsigned smem_u32(const void* p) {
    unsigned a;
    asm("{ .reg .u64 t; cvta.to.shared.u64 t, %1; cvt.u32.u64 %0, t; }" : "=r"(a) : "l"(p));
    return a;
}
__device__ __forceinline__ void ldsm_x4(unsigned& r0, unsigned& r1, unsigned& r2,
                                        unsigned& r3, unsigned addr) {
    asm volatile("ldmatrix.sync.aligned.m8n8.x4.shared.b16 {%0,%1,%2,%3}, [%4];"
        : "=r"(r0), "=r"(r1), "=r"(r2), "=r"(r3) : "r"(addr));
}
__device__ __forceinline__ void mma_s8(int* d, unsigned a0, unsigned a1, unsigned a2,
                                       unsigned a3, unsigned b0, unsigned b1) {
    asm volatile("mma.sync.aligned.m16n8k32.row.col.s32.u8.s8.s32 "
        "{%0,%1,%2,%3}, {%4,%5,%6,%7}, {%8,%9}, {%0,%1,%2,%3};"
        : "+r"(d[0]), "+r"(d[1]), "+r"(d[2]), "+r"(d[3])
        : "r"(a0), "r"(a1), "r"(a2), "r"(a3), "r"(b0), "r"(b1));
}
__device__ __forceinline__ void mma_f16(float* d, unsigned a0, unsigned a1, unsigned a2,
                                        unsigned a3, unsigned b0, unsigned b1) {
    asm volatile("mma.sync.aligned.m16n8k16.row.col.f32.f16.f16.f32 "
        "{%0,%1,%2,%3}, {%4,%5,%6,%7}, {%8,%9}, {%0,%1,%2,%3};"
        : "+f"(d[0]), "+f"(d[1]), "+f"(d[2]), "+f"(d[3])
        : "r"(a0), "r"(a1), "r"(a2), "r"(a3), "r"(b0), "r"(b1));
}

// ================= quantizers (round-half-even, match jnp) =================
__device__ __forceinline__ float qhtanh_f(float x) {
    float c = fminf(fmaxf(x, -10.0f), 10.0f);
    float r = rintf(__fdiv_rn(c, HT_S));
    r = fminf(fmaxf(r, -127.0f), 127.0f);
    return r * HT_S;
}
__device__ __forceinline__ unsigned qrelu_code(float x) {
    float c = fminf(fmaxf(x, 0.0f), 10.0f);
    float r = rintf(__fdiv_rn(c, R_S));
    return (unsigned)(int)fminf(r, 255.0f);
}
__device__ __forceinline__ unsigned long long pack_dup(float v) {
    unsigned long long r;
    asm("mov.b64 %0, {%1, %1};" : "=l"(r) : "f"(v));
    return r;
}
__device__ __forceinline__ unsigned long long fma2(unsigned long long a, unsigned long long b,
                                                   unsigned long long c) {
    unsigned long long d;
    asm("fma.rn.f32x2 %0, %1, %2, %3;" : "=l"(d) : "l"(a), "l"(b), "l"(c));
    return d;
}
__device__ __forceinline__ void unpack2(unsigned long long v, float& lo, float& hi) {
    asm("mov.b64 {%0, %1}, %2;" : "=f"(lo), "=f"(hi) : "l"(v));
}

// ================= prep1: fused weight prep + x transpose (block roles) ======
#define PREP1_GRID 3546
__global__ void prep1_kernel(const float* __restrict__ w, const float* __restrict__ ds_w,
                             const float* __restrict__ x,
                             float* __restrict__ wsc, uint2* __restrict__ bfi,
                             uint2* __restrict__ bfh, float* __restrict__ dsq,
                             unsigned* __restrict__ xhi, unsigned* __restrict__ xmid,
                             unsigned* __restrict__ xlo) {
    int b = blockIdx.x, tid = threadIdx.x;
    __shared__ float red[256];
    __shared__ unsigned short shi[64][66], smd[64][66], slo[64][66];

    if (b < 256) {                              // ---- weight scale (AVE)
        const float* wc = w + b*576;
        float s = 0.f;
        for (int e = tid; e < 576; e += 256) s += fabsf(wc[e]);
        red[tid] = s;
        __syncthreads();
        for (int off = 128; off > 0; off >>= 1) {
            if (tid < off) red[tid] += red[tid+off];
            __syncthreads();
        }
        if (tid == 0) wsc[b] = fmaxf(red[0] * (1.0f/576.0f), 2e-16f);
    } else if (b < 310) {                       // ---- int-stage B fragments
        int idx = (b-256)*256 + tid;
        if (idx < 3*9*2*8*32) {
            int lane = idx & 31;
            int nt   = (idx >> 5) & 7;
            int c    = (idx >> 8) & 1;
            int tap  = (idx >> 9) % 9;
            int s    = idx / 4608;
            int co   = nt*8 + (lane >> 2);
            unsigned b0 = 0, b1 = 0;
            #pragma unroll
            for (int j = 0; j < 4; j++) {
                int ci0 = c*32 + (lane & 3)*4 + j;
                float v0 = w[(((s+1)*64 + co)*64 + ci0)*9 + tap];
                float v1 = w[(((s+1)*64 + co)*64 + ci0 + 16)*9 + tap];
                b0 |= ((v0 >= 0.f) ? 0x01u : 0xFFu) << (8*j);
                b1 |= ((v1 >= 0.f) ? 0x01u : 0xFFu) << (8*j);
            }
            bfi[idx] = make_uint2(b0, b1);
        }
    } else if (b < 346) {                       // ---- stage0 f16 B fragments
        int idx = (b-310)*256 + tid;
        if (idx < 9*4*8*32) {
            int lane = idx & 31;
            int nt   = (idx >> 5) & 7;
            int c    = (idx >> 8) & 3;
            int tap  = idx >> 10;
            int co   = nt*8 + (lane >> 2);
            int ci   = c*16 + (lane & 3)*2;
            unsigned h00 = (w[((0*64+co)*64 + ci  )*9 + tap] >= 0.f) ? 0x3C00u : 0xBC00u;
            unsigned h01 = (w[((0*64+co)*64 + ci+1)*9 + tap] >= 0.f) ? 0x3C00u : 0xBC00u;
            unsigned h10 = (w[((0*64+co)*64 + ci+8)*9 + tap] >= 0.f) ? 0x3C00u : 0xBC00u;
            unsigned h11 = (w[((0*64+co)*64 + ci+9)*9 + tap] >= 0.f) ? 0x3C00u : 0xBC00u;
            bfh[idx] = make_uint2(h00 | (h01 << 16), h10 | (h11 << 16));
        }
    } else if (b < 410) {                       // ---- int8 1x1 quant
        int co = b - 346;
        red[tid] = (tid < 64) ? fabsf(ds_w[co*64 + tid]) : 0.f;
        __syncthreads();
        for (int off = 128; off > 0; off >>= 1) {
            if (tid < off) red[tid] = fmaxf(red[tid], red[tid+off]);
            __syncthreads();
        }
        if (tid < 64) {
            float scale = fmaxf(red[0], 2e-16f) / 127.0f;
            float q = fminf(fmaxf(rintf(__fdiv_rn(ds_w[co*64 + tid], scale)), -127.f), 127.f) * scale;
            dsq[tid*64 + co] = q;
        }
    } else {                                    // ---- transpose x -> hi/mid/lo
        int blk = b - 410;                      // 0..3135
        int n = blk / 196;
        int pix0 = (blk % 196) * 64;
        #pragma unroll
        for (int pass = 0; pass < 16; pass++) {
            int idx = tid + pass*256;
            int c = idx >> 6, p = idx & 63;
            float v = x[((size_t)n*64 + c)*HWHW + pix0 + p];
            __half h = __float2half_rn(v);
            float r1 = v - __half2float(h);
            __half m = __float2half_rn(r1 * 2048.0f);
            float r2 = r1 - __half2float(m) * SC_M;
            __half l = __float2half_rn(r2 * 4194304.0f);
            shi[p][c] = __half_as_ushort(h);
            smd[p][c] = __half_as_ushort(m);
            slo[p][c] = __half_as_ushort(l);
        }
        __syncthreads();
        int px = tid >> 2, part = tid & 3;
        size_t base = ((size_t)n*HWHW + pix0 + px)*32 + part*8;
        #pragma unroll
        for (int i = 0; i < 8; i++) {
            int c = part*16 + i*2;
            xhi [base+i] = (unsigned)shi[px][c] | ((unsigned)shi[px][c+1] << 16);
            xmid[base+i] = (unsigned)smd[px][c] | ((unsigned)smd[px][c+1] << 16);
            xlo [base+i] = (unsigned)slo[px][c] | ((unsigned)slo[px][c+1] << 16);
        }
    }
}

// ================= prep2: BN coefficients =================
__global__ void prep2_kernel(const float* __restrict__ g, const float* __restrict__ b,
                             const float* __restrict__ m, const float* __restrict__ v,
                             const float* __restrict__ wsc,
                             float* __restrict__ A, float* __restrict__ B,
                             float* __restrict__ inv4, float* __restrict__ bias4) {
    int i = threadIdx.x;   // 320
    float iv = g[i] * __fdiv_rn(1.0f, __fsqrt_rn(v[i] + 1e-5f));
    float bias = b[i] - m[i] * iv;
    if (i < 256) {
        int s = i >> 6;
        float a = wsc[i] * iv;
        if (s > 0) a *= R_S;
        A[i] = a;
        B[i] = bias;
    } else {
        inv4[i-256] = iv;
        bias4[i-256] = bias;
    }
}

// -------- 1x1 conv (downsample) + bn4 + qhtanh -> NHWC packed s8 ------
__global__ __launch_bounds__(256, 2)
void conv1x1_kernel(const float* __restrict__ x, const float* __restrict__ wt,
                    const float* __restrict__ bninv, const float* __restrict__ bnbias,
                    unsigned* __restrict__ out) {
    int b  = blockIdx.x;          // 784 = 16 * 49
    int n  = b / 49;
    int p0 = (b - n*49) * 256;
    __shared__ float xs[16][256];
    __shared__ __align__(8) float ws[16][64];
    __shared__ unsigned s_out[256][16];
    int t   = threadIdx.x;
    int pl  = t & 63;
    int cog = t >> 6;
    unsigned long long acc2[4][8];
    #pragma unroll
    for (int j = 0; j < 4; j++)
        #pragma unroll
        for (int k2 = 0; k2 < 8; k2++) acc2[j][k2] = 0ULL;

    const float* xN = x + (size_t)n*CC*HWHW + p0;
    for (int c0 = 0; c0 < CC; c0 += 16) {
        __syncthreads();
        #pragma unroll
        for (int r = 0; r < 16; r++) xs[r][t] = xN[(size_t)(c0+r)*HWHW + t];
        #pragma unroll
        for (int r = 0; r < 4; r++) {
            int e = t + r*256;
            ws[e>>6][e&63] = wt[(c0 + (e>>6))*64 + (e&63)];
        }
        __syncthreads();
        #pragma unroll
        for (int ci = 0; ci < 16; ci++) {
            unsigned long long w2[8];
            #pragma unroll
            for (int k2 = 0; k2 < 8; k2++)
                w2[k2] = *(const unsigned long long*)&ws[ci][cog*16 + 2*k2];
            #pragma unroll
            for (int j = 0; j < 4; j++) {
                unsigned long long xv2 = pack_dup(xs[ci][pl + 64*j]);
                #pragma unroll
                for (int k2 = 0; k2 < 8; k2++)
                    acc2[j][k2] = fma2(xv2, w2[k2], acc2[j][k2]);
            }
        }
    }
    #pragma unroll
    for (int j = 0; j < 4; j++) {
        unsigned words[4] = {0,0,0,0};
        #pragma unroll
        for (int k2 = 0; k2 < 8; k2++) {
            float a0, a1;
            unpack2(acc2[j][k2], a0, a1);
            #pragma unroll
            for (int h = 0; h < 2; h++) {
                int k = 2*k2 + h;
                int co = cog*16 + k;
                float v = fmaf(h ? a1 : a0, bninv[co], bnbias[co]);
                float c = fminf(fmaxf(v, -10.0f), 10.0f);
                float r = fminf(fmaxf(rintf(__fdiv_rn(c, HT_S)), -127.f), 127.f);
                words[k>>2] |= (((unsigned)(int)r) & 0xFFu) << (8*(k&3));
            }
        }
        #pragma unroll
        for (int q = 0; q < 4; q++) s_out[pl + 64*j][cog*4 + q] = words[q];
    }
    __syncthreads();
    uint4* gdst = (uint4*)(out + ((size_t)n*HWHW + p0 + t)*16);
    const uint4* srow = (const uint4*)&s_out[t][0];
    #pragma unroll
    for (int q = 0; q < 4; q++) gdst[q] = srow[q];
}

// ================ HMMA stage 0: 128 threads, M=32/warp, 3 streamed passes ======
// 4 warps; warp w owns h-rows 2w and 2w+1 (two independent m16 tiles).
// smem: sB uint2[9216] (73728B) | halo u32[180][36] (25920B) => 99648B, 2 CTAs/SM
#define HPITCH_H 36
__global__ __launch_bounds__(128, 2)
void conv3x3_hmma0(const unsigned* __restrict__ xhi, const unsigned* __restrict__ xmid,
                   const unsigned* __restrict__ xlo,
                   const uint2* __restrict__ bfrag,
                   const float* __restrict__ Acoef, const float* __restrict__ Bcoef,
                   unsigned* __restrict__ outp) {
    extern __shared__ char dsm[];
    uint2* sBf = (uint2*)dsm;
    unsigned* halo = (unsigned*)(dsm + 73728);
    __shared__ float sAc[64], sBc[64];

    int tid = threadIdx.x;
    int wid = tid >> 5;          // 0..3
    int lane = tid & 31;
    int n  = blockIdx.z;
    int h0 = blockIdx.y * 8;
    int w0 = blockIdx.x * 16;

    if (tid < 64) { sAc[tid] = Acoef[tid]; sBc[tid] = Bcoef[tid]; }
    {
        const uint4* src = (const uint4*)bfrag;
        uint4* dst = (uint4*)sBf;
        #pragma unroll
        for (int i = 0; i < 36; i++) dst[tid + i*128] = src[tid + i*128];
    }
    unsigned haloAddr = smem_u32(halo);
    unsigned aBase0 = haloAddr + (unsigned)(((wid*2)*18 + (lane & 15))*144 + (lane >> 4)*16);
    unsigned aBase1 = aBase0 + 18*144;

    float acc[2][8][4];
    #pragma unroll
    for (int hr = 0; hr < 2; hr++)
        #pragma unroll
        for (int nt = 0; nt < 8; nt++)
            #pragma unroll
            for (int q = 0; q < 4; q++) acc[hr][nt][q] = 0.f;

    #pragma unroll 1
    for (int pass = 0; pass < 3; pass++) {
        const unsigned* xsrc = (pass == 0) ? xlo : (pass == 1) ? xmid : xhi;
        __syncthreads();
        for (int e = tid; e < 5760; e += 128) {
            int r = e / 576, rr = e % 576, c = rr >> 5, q = rr & 31;
            int hh = h0 - 1 + r, ww = w0 - 1 + c;
            unsigned v = 0;
            if ((unsigned)hh < HH && (unsigned)ww < WW)
                v = xsrc[((size_t)n*HWHW + (size_t)hh*WW + ww)*32 + q];
            halo[(r*18 + c)*HPITCH_H + q] = v;
        }
        __syncthreads();
        #pragma unroll 1
        for (int dy = 0; dy < 3; dy++)
        #pragma unroll
        for (int dx = 0; dx < 3; dx++) {
            unsigned off = (unsigned)((dy*18 + dx)*144);
            #pragma unroll
            for (int c = 0; c < 4; c++) {
                unsigned a0, a1, a2, a3, b0, b1, b2, b3;
                ldsm_x4(a0, a1, a2, a3, aBase0 + off + c*32);
                ldsm_x4(b0, b1, b2, b3, aBase1 + off + c*32);
                const uint2* bp = sBf + ((dy*3 + dx)*4 + c)*256 + lane;
                #pragma unroll
                for (int nt = 0; nt < 8; nt++) {
                    uint2 b = bp[nt*32];
                    mma_f16(acc[0][nt], a0, a1, a2, a3, b.x, b.y);
                    mma_f16(acc[1][nt], b0, b1, b2, b3, b.x, b.y);
                }
            }
        }
        if (pass < 2) {
            #pragma unroll
            for (int hr = 0; hr < 2; hr++)
                #pragma unroll
                for (int nt = 0; nt < 8; nt++)
                    #pragma unroll
                    for (int q = 0; q < 4; q++) acc[hr][nt][q] *= SC_M;
        }
    }

    // epilogue: x = (hi + mid*2^-11) + lo*2^-22 read from gmem (exact)
    unsigned short pairs[2][2][8];
    #pragma unroll
    for (int hr = 0; hr < 2; hr++) {
        int hrow = h0 + wid*2 + hr;
        #pragma unroll
        for (int h2 = 0; h2 < 2; h2++) {
            int px = (lane >> 2) + 8*h2;
            size_t gw = ((size_t)n*HWHW + (size_t)hrow*WW + (w0 + px))*32 + (lane & 3);
            #pragma unroll
            for (int nt = 0; nt < 8; nt++) {
                unsigned wh = __ldg(xhi  + gw + nt*4);
                unsigned wm = __ldg(xmid + gw + nt*4);
                unsigned wl = __ldg(xlo  + gw + nt*4);
                unsigned pr = 0;
                #pragma unroll
                for (int j = 0; j < 2; j++) {
                    int co = nt*8 + (lane & 3)*2 + j;
                    float v = fmaf(acc[hr][nt][2*h2 + j], sAc[co], sBc[co]);
                    __half xh = __ushort_as_half((unsigned short)((wh >> (16*j)) & 0xFFFF));
                    __half xm = __ushort_as_half((unsigned short)((wm >> (16*j)) & 0xFFFF));
                    __half xl = __ushort_as_half((unsigned short)((wl >> (16*j)) & 0xFFFF));
                    float xv = (__half2float(xh) + __half2float(xm) * SC_M)
                             + __half2float(xl) * SC_L;
                    float r = qhtanh_f(v) + qhtanh_f(xv);
                    pr |= qrelu_code(r) << (8*j);
                }
                pairs[hr][h2][nt] = (unsigned short)pr;
            }
        }
    }
    __syncthreads();
    unsigned short* stag = (unsigned short*)halo;
    #pragma unroll
    for (int hr = 0; hr < 2; hr++)
        #pragma unroll
        for (int h2 = 0; h2 < 2; h2++) {
            int px = (lane >> 2) + 8*h2;
            int pxl = (wid*2 + hr)*16 + px;
            #pragma unroll
            for (int nt = 0; nt < 8; nt++)
                stag[pxl*32 + nt*4 + (lane & 3)] = pairs[hr][h2][nt];
        }
    __syncthreads();
    {
        int pxl = tid;                  // 128 px, one per thread
        int h = h0 + (pxl >> 4), w = w0 + (pxl & 15);
        const uint4* src = (const uint4*)((char*)halo + pxl*64);
        uint4* dst = (uint4*)(outp + ((size_t)n*HWHW + (size_t)h*WW + w)*16);
        #pragma unroll
        for (int q = 0; q < 4; q++) dst[q] = src[q];
    }
}

// ================ IMMA int stages: 128 threads, M=32/warp (EPI 0/1/3) ========
// smem: sB uint2[4608] (36864B) | halo u32[180][20] (14400B) => 51264B, 4 CTAs/SM
#define HPITCH_I 20
template<int EPI>
__global__ __launch_bounds__(128, 4)
void conv3x3_imma(const unsigned* __restrict__ act_in, const uint2* __restrict__ bfrag,
                  const float* __restrict__ Acoef, const float* __restrict__ Bcoef,
                  const unsigned* __restrict__ e1, unsigned* __restrict__ outp) {
    extern __shared__ char dsm[];
    uint2* sBf = (uint2*)dsm;
    unsigned* halo = (unsigned*)(dsm + 36864);
    __shared__ float sAc[64], sBc[64];

    int tid = threadIdx.x;
    int wid = tid >> 5;          // 0..3
    int lane = tid & 31;
    int n  = blockIdx.z;
    int h0 = blockIdx.y * 8;
    int w0 = blockIdx.x * 16;

    if (tid < 64) { sAc[tid] = Acoef[tid]; sBc[tid] = Bcoef[tid]; }
    {
        const uint4* src = (const uint4*)bfrag;
        uint4* dst = (uint4*)sBf;
        #pragma unroll
        for (int i = 0; i < 18; i++) dst[tid + i*128] = src[tid + i*128];
    }
    const unsigned* inN = act_in + (size_t)n*HWHW*16;
    for (int e = tid; e < 2880; e += 128) {
        int r = e / 288, rr = e % 288, c = rr >> 4, q = rr & 15;
        int hh = h0 - 1 + r, ww = w0 - 1 + c;
        unsigned v = 0;
        if ((unsigned)hh < HH && (unsigned)ww < WW)
            v = inN[((size_t)hh*WW + ww)*16 + q];
        halo[(r*18 + c)*HPITCH_I + q] = v;
    }
    __syncthreads();

    unsigned haloAddr = smem_u32(halo);
    unsigned aBase0 = haloAddr + (unsigned)(((wid*2)*18 + (lane & 15))*80 + (lane >> 4)*16);
    unsigned aBase1 = aBase0 + 18*80;

    int acc[2][8][4];
    #pragma unroll
    for (int hr = 0; hr < 2; hr++)
        #pragma unroll
        for (int nt = 0; nt < 8; nt++)
            #pragma unroll
            for (int q = 0; q < 4; q++) acc[hr][nt][q] = 0;

    #pragma unroll 1
    for (int dy = 0; dy < 3; dy++)
    #pragma unroll
    for (int dx = 0; dx < 3; dx++) {
        unsigned off = (unsigned)((dy*18 + dx)*80);
        #pragma unroll
        for (int c = 0; c < 2; c++) {
            unsigned a0, a1, a2, a3, b0, b1, b2, b3;
            ldsm_x4(a0, a1, a2, a3, aBase0 + off + c*32);
            ldsm_x4(b0, b1, b2, b3, aBase1 + off + c*32);
            const uint2* bp = sBf + ((dy*3 + dx)*2 + c)*256 + lane;
            #pragma unroll
            for (int nt = 0; nt < 8; nt++) {
                uint2 b = bp[nt*32];
                mma_s8(acc[0][nt], a0, a1, a2, a3, b.x, b.y);
                mma_s8(acc[1][nt], b0, b1, b2, b3, b.x, b.y);
            }
        }
    }

    // epilogue -> u8 code pairs
    unsigned short pairs[2][2][8];
    #pragma unroll
    for (int hr = 0; hr < 2; hr++) {
        int hrow = wid*2 + hr;
        int ctr_row = (hrow + 1)*18;
        #pragma unroll
        for (int h2 = 0; h2 < 2; h2++) {
            int px = (lane >> 2) + 8*h2;
            int ctr = (ctr_row + px + 1)*HPITCH_I;
            size_t pixw = ((size_t)n*HWHW + (size_t)(h0 + hrow)*WW + (w0 + px))*16;
            int wsel = (lane & 3) >> 1;
            int b0 = ((lane & 3) & 1)*2;
            #pragma unroll
            for (int nt = 0; nt < 8; nt++) {
                unsigned inw = halo[ctr + 2*nt + wsel];
                unsigned ew = 0;
                if (EPI == 1 || EPI == 3) ew = e1[pixw + 2*nt + wsel];
                unsigned pr = 0;
                #pragma unroll
                for (int j = 0; j < 2; j++) {
                    int co = nt*8 + (lane & 3)*2 + j;
                    float v = fmaf((float)acc[hr][nt][2*h2 + j], sAc[co], sBc[co]);
                    int byte = b0 + j;
                    float in_val = (float)((inw >> (8*byte)) & 255u) * R_S;
                    float r;
                    if (EPI == 0) {
                        r = qhtanh_f(v) + qhtanh_f(in_val);
                    } else if (EPI == 1) {
                        int ec = (int)(ew << (24 - 8*byte)) >> 24;
                        float tq = qhtanh_f(v) + (float)ec * HT_S;
                        r = qhtanh_f(tq) + qhtanh_f(in_val);
                    } else {
                        float ev = (float)((ew >> (8*byte)) & 255u) * R_S;
                        float tq = qhtanh_f(v) + qhtanh_f(ev);
                        r = qhtanh_f(in_val) + qhtanh_f(tq);
                    }
                    pr |= qrelu_code(r) << (8*j);
                }
                pairs[hr][h2][nt] = (unsigned short)pr;
            }
        }
    }
    __syncthreads();                       // all halo reads done; reuse as staging
    unsigned short* stag = (unsigned short*)halo;
    #pragma unroll
    for (int hr = 0; hr < 2; hr++)
        #pragma unroll
        for (int h2 = 0; h2 < 2; h2++) {
            int px = (lane >> 2) + 8*h2;
            int pxl = (wid*2 + hr)*16 + px;
            #pragma unroll
            for (int nt = 0; nt < 8; nt++)
                stag[pxl*32 + nt*4 + (lane & 3)] = pairs[hr][h2][nt];
        }
    __syncthreads();
    {
        int pxl = tid;
        int h = h0 + (pxl >> 4), w = w0 + (pxl & 15);
        const uint4* src = (const uint4*)((char*)halo + pxl*64);
        uint4* dst = (uint4*)(outp + ((size_t)n*HWHW + (size_t)h*WW + w)*16);
        #pragma unroll
        for (int q = 0; q < 4; q++) dst[q] = src[q];
    }
}

// -------- final: u8 NHWC codes -> fp32 NCHW (out = code * R_S) --------
__global__ void out_expand_kernel(const unsigned* __restrict__ codes,
                                  float* __restrict__ out) {
    __shared__ unsigned st[64][17];
    int blk = blockIdx.x;             // 16*196
    int n = blk / 196;
    int pix0 = (blk % 196) * 64;
    int tid = threadIdx.x;
    #pragma unroll
    for (int i = 0; i < 4; i++) {
        int e = tid + i*256;
        int px = e >> 4, q = e & 15;
        st[px][q] = codes[((size_t)n*HWHW + pix0 + px)*16 + q];
    }
    __syncthreads();
    int c = tid >> 2, qq = tid & 3;
    float* dst = out + ((size_t)n*64 + c)*HWHW + pix0 + qq*16;
    #pragma unroll
    for (int i = 0; i < 16; i++) {
        unsigned w = st[qq*16 + i][c >> 2];
        dst[i] = (float)((w >> (8*(c & 3))) & 255u) * R_S;
    }
}

// -------------------- host launcher --------------------------------
extern "C" void kernel_launch(void* const* d_in, const int* in_sizes, int n_in,
                              void* d_out, int out_size) {
    const float* x      = (const float*)d_in[0];
    const float* conv_w = (const float*)d_in[1];
    const float* ds_w   = (const float*)d_in[2];
    const float* bng    = (const float*)d_in[3];
    const float* bnb    = (const float*)d_in[4];
    const float* bnm    = (const float*)d_in[5];
    const float* bnvv   = (const float*)d_in[6];
    float* out = (float*)d_out;

    unsigned *act1, *act2, *act3, *act4, *idq, *xhi, *xmid, *xlo;
    uint2 *bfi, *bfh;
    float *dsq, *wsc, *A, *B, *inv4, *bias4;
    cudaGetSymbolAddress((void**)&act1, g_act1);
    cudaGetSymbolAddress((void**)&act2, g_act2);
    cudaGetSymbolAddress((void**)&act3, g_act3);
    cudaGetSymbolAddress((void**)&act4, g_act4);
    cudaGetSymbolAddress((void**)&idq,  g_idq);
    cudaGetSymbolAddress((void**)&xhi,  g_xhi);
    cudaGetSymbolAddress((void**)&xmid, g_xmid);
    cudaGetSymbolAddress((void**)&xlo,  g_xlo);
    cudaGetSymbolAddress((void**)&bfi,  g_bfi);
    cudaGetSymbolAddress((void**)&bfh,  g_bfh);
    cudaGetSymbolAddress((void**)&dsq,  g_dsq);
    cudaGetSymbolAddress((void**)&wsc,  g_wsc);
    cudaGetSymbolAddress((void**)&A,    g_A);
    cudaGetSymbolAddress((void**)&B,    g_B);
    cudaGetSymbolAddress((void**)&inv4, g_bninv4);
    cudaGetSymbolAddress((void**)&bias4,g_bnbias4);

    const int SMEMI = 36864 + 14400;            // 51,264 -> up to 4 CTAs/SM
    const int SMEM0 = 73728 + 25920;            // 99,648 -> 2 CTAs/SM
    cudaFuncSetAttribute(conv3x3_hmma0,   cudaFuncAttributeMaxDynamicSharedMemorySize, SMEM0);
    cudaFuncSetAttribute(conv3x3_imma<0>, cudaFuncAttributeMaxDynamicSharedMemorySize, SMEMI);
    cudaFuncSetAttribute(conv3x3_imma<1>, cudaFuncAttributeMaxDynamicSharedMemorySize, SMEMI);
    cudaFuncSetAttribute(conv3x3_imma<3>, cudaFuncAttributeMaxDynamicSharedMemorySize, SMEMI);

    // launch #1: fused prep; #2: bn coefs; #3: conv1x1; #4: hmma0 (profiled)
    prep1_kernel<<<PREP1_GRID, 256>>>(conv_w, ds_w, x, wsc, bfi, bfh, dsq, xhi, xmid, xlo);
    prep2_kernel<<<1, 320>>>(bng, bnb, bnm, bnvv, wsc, A, B, inv4, bias4);
    conv1x1_kernel<<<784, 256>>>(x, dsq, inv4, bias4, idq);

    dim3 grid(7, 14, NN);   // 16w x 8h tiles
    conv3x3_hmma0<<<grid, 128, SMEM0>>>(xhi, xmid, xlo, bfh, A + 0*CC, B + 0*CC, act1);
    conv3x3_imma<1><<<grid, 128, SMEMI>>>(act1, bfi + 0*4608, A + 1*CC, B + 1*CC, idq,  act2);
    conv3x3_imma<0><<<grid, 128, SMEMI>>>(act2, bfi + 1*4608, A + 2*CC, B + 2*CC, nullptr, act3);
    conv3x3_imma<3><<<grid, 128, SMEMI>>>(act3, bfi + 2*4608, A + 3*CC, B + 3*CC, act2, act4);
    out_expand_kernel<<<16*196, 256>>>(act4, out);
}

// round 14
// speedup vs baseline: 1.0606x; 1.0606x over previous
#include <cuda_runtime.h>
#include <cuda_fp16.h>

#define NN 16
#define CC 64
#define HH 112
#define WW 112
#define HWHW (HH*WW)               // 12544
#define PKW (NN*16*HWHW)           // u8-packed NHWC act words
#define XHW (NN*HWHW*32)           // f16-packed x words (hi/mid/lo)

#define R_S  (10.0f/255.0f)
#define HT_S (10.0f/127.0f)
#define SC_M (1.0f/2048.0f)        // 2^-11
#define SC_L (1.0f/4194304.0f)     // 2^-22

// -------- device scratch ----------
__device__ unsigned g_act1[PKW];
__device__ unsigned g_act2[PKW];
__device__ unsigned g_act3[PKW];
__device__ unsigned g_act4[PKW];
__device__ unsigned g_idq [PKW];
__device__ unsigned g_xhi [XHW];
__device__ unsigned g_xmid[XHW];
__device__ unsigned g_xlo [XHW];
__device__ __align__(16) uint2 g_bfi[3*9*2*8*32];   // int-stage B fragments
__device__ __align__(16) uint2 g_bfh[9*4*8*32];     // stage0 f16 B fragments
__device__ float    g_dsq [CC*CC];
__device__ float    g_wsc [4*CC];
__device__ float    g_A   [4*CC];
__device__ float    g_B   [4*CC];
__device__ float    g_bninv4 [CC];
__device__ float    g_bnbias4[CC];

// ================= helpers =================
__device__ __forceinline__ unsigned smem_u32(const void* p) {
    unsigned a;
    asm("{ .reg .u64 t; cvta.to.shared.u64 t, %1; cvt.u32.u64 %0, t; }" : "=r"(a) : "l"(p));
    return a;
}
__device__ __forceinline__ void ldsm_x4(unsigned& r0, unsigned& r1, unsigned& r2,
                                        unsigned& r3, unsigned addr) {
    asm volatile("ldmatrix.sync.aligned.m8n8.x4.shared.b16 {%0,%1,%2,%3}, [%4];"
        : "=r"(r0), "=r"(r1), "=r"(r2), "=r"(r3) : "r"(addr));
}
__device__ __forceinline__ void mma_s8(int* d, unsigned a0, unsigned a1, unsigned a2,
                                       unsigned a3, unsigned b0, unsigned b1) {
    asm volatile("mma.sync.aligned.m16n8k32.row.col.s32.u8.s8.s32 "
        "{%0,%1,%2,%3}, {%4,%5,%6,%7}, {%8,%9}, {%0,%1,%2,%3};"
        : "+r"(d[0]), "+r"(d[1]), "+r"(d[2]), "+r"(d[3])
        : "r"(a0), "r"(a1), "r"(a2), "r"(a3), "r"(b0), "r"(b1));
}
__device__ __forceinline__ void mma_f16(float* d, unsigned a0, unsigned a1, unsigned a2,
                                        unsigned a3, unsigned b0, unsigned b1) {
    asm volatile("mma.sync.aligned.m16n8k16.row.col.f32.f16.f16.f32 "
        "{%0,%1,%2,%3}, {%4,%5,%6,%7}, {%8,%9}, {%0,%1,%2,%3};"
        : "+f"(d[0]), "+f"(d[1]), "+f"(d[2]), "+f"(d[3])
        : "r"(a0), "r"(a1), "r"(a2), "r"(a3), "r"(b0), "r"(b1));
}

// ================= quantizers (round-half-even, match jnp) =================
__device__ __forceinline__ float qhtanh_f(float x) {
    float c = fminf(fmaxf(x, -10.0f), 10.0f);
    float r = rintf(__fdiv_rn(c, HT_S));
    r = fminf(fmaxf(r, -127.0f), 127.0f);
    return r * HT_S;
}
__device__ __forceinline__ unsigned qrelu_code(float x) {
    float c = fminf(fmaxf(x, 0.0f), 10.0f);
    float r = rintf(__fdiv_rn(c, R_S));
    return (unsigned)(int)fminf(r, 255.0f);
}
__device__ __forceinline__ unsigned long long pack_dup(float v) {
    unsigned long long r;
    asm("mov.b64 %0, {%1, %1};" : "=l"(r) : "f"(v));
    return r;
}
__device__ __forceinline__ unsigned long long fma2(unsigned long long a, unsigned long long b,
                                                   unsigned long long c) {
    unsigned long long d;
    asm("fma.rn.f32x2 %0, %1, %2, %3;" : "=l"(d) : "l"(a), "l"(b), "l"(c));
    return d;
}
__device__ __forceinline__ void unpack2(unsigned long long v, float& lo, float& hi) {
    asm("mov.b64 {%0, %1}, %2;" : "=f"(lo), "=f"(hi) : "l"(v));
}

// ================= prep1: fused weight prep + x transpose (block roles) ======
#define PREP1_GRID 3546
__global__ void prep1_kernel(const float* __restrict__ w, const float* __restrict__ ds_w,
                             const float* __restrict__ x,
                             float* __restrict__ wsc, uint2* __restrict__ bfi,
                             uint2* __restrict__ bfh, float* __restrict__ dsq,
                             unsigned* __restrict__ xhi, unsigned* __restrict__ xmid,
                             unsigned* __restrict__ xlo) {
    int b = blockIdx.x, tid = threadIdx.x;
    __shared__ float red[256];
    __shared__ unsigned short shi[64][66], smd[64][66], slo[64][66];

    if (b < 256) {                              // ---- weight scale (AVE)
        const float* wc = w + b*576;
        float s = 0.f;
        for (int e = tid; e < 576; e += 256) s += fabsf(wc[e]);
        red[tid] = s;
        __syncthreads();
        for (int off = 128; off > 0; off >>= 1) {
            if (tid < off) red[tid] += red[tid+off];
            __syncthreads();
        }
        if (tid == 0) wsc[b] = fmaxf(red[0] * (1.0f/576.0f), 2e-16f);
    } else if (b < 310) {                       // ---- int-stage B fragments
        int idx = (b-256)*256 + tid;
        if (idx < 3*9*2*8*32) {
            int lane = idx & 31;
            int nt   = (idx >> 5) & 7;
            int c    = (idx >> 8) & 1;
            int tap  = (idx >> 9) % 9;
            int s    = idx / 4608;
            int co   = nt*8 + (lane >> 2);
            unsigned b0 = 0, b1 = 0;
            #pragma unroll
            for (int j = 0; j < 4; j++) {
                int ci0 = c*32 + (lane & 3)*4 + j;
                float v0 = w[(((s+1)*64 + co)*64 + ci0)*9 + tap];
                float v1 = w[(((s+1)*64 + co)*64 + ci0 + 16)*9 + tap];
                b0 |= ((v0 >= 0.f) ? 0x01u : 0xFFu) << (8*j);
                b1 |= ((v1 >= 0.f) ? 0x01u : 0xFFu) << (8*j);
            }
            bfi[idx] = make_uint2(b0, b1);
        }
    } else if (b < 346) {                       // ---- stage0 f16 B fragments
        int idx = (b-310)*256 + tid;
        if (idx < 9*4*8*32) {
            int lane = idx & 31;
            int nt   = (idx >> 5) & 7;
            int c    = (idx >> 8) & 3;
            int tap  = idx >> 10;
            int co   = nt*8 + (lane >> 2);
            int ci   = c*16 + (lane & 3)*2;
            unsigned h00 = (w[((0*64+co)*64 + ci  )*9 + tap] >= 0.f) ? 0x3C00u : 0xBC00u;
            unsigned h01 = (w[((0*64+co)*64 + ci+1)*9 + tap] >= 0.f) ? 0x3C00u : 0xBC00u;
            unsigned h10 = (w[((0*64+co)*64 + ci+8)*9 + tap] >= 0.f) ? 0x3C00u : 0xBC00u;
            unsigned h11 = (w[((0*64+co)*64 + ci+9)*9 + tap] >= 0.f) ? 0x3C00u : 0xBC00u;
            bfh[idx] = make_uint2(h00 | (h01 << 16), h10 | (h11 << 16));
        }
    } else if (b < 410) {                       // ---- int8 1x1 quant
        int co = b - 346;
        red[tid] = (tid < 64) ? fabsf(ds_w[co*64 + tid]) : 0.f;
        __syncthreads();
        for (int off = 128; off > 0; off >>= 1) {
            if (tid < off) red[tid] = fmaxf(red[tid], red[tid+off]);
            __syncthreads();
        }
        if (tid < 64) {
            float scale = fmaxf(red[0], 2e-16f) / 127.0f;
            float q = fminf(fmaxf(rintf(__fdiv_rn(ds_w[co*64 + tid], scale)), -127.f), 127.f) * scale;
            dsq[tid*64 + co] = q;
        }
    } else {                                    // ---- transpose x -> hi/mid/lo
        int blk = b - 410;                      // 0..3135
        int n = blk / 196;
        int pix0 = (blk % 196) * 64;
        #pragma unroll
        for (int pass = 0; pass < 16; pass++) {
            int idx = tid + pass*256;
            int c = idx >> 6, p = idx & 63;
            float v = x[((size_t)n*64 + c)*HWHW + pix0 + p];
            __half h = __float2half_rn(v);
            float r1 = v - __half2float(h);
            __half m = __float2half_rn(r1 * 2048.0f);
            float r2 = r1 - __half2float(m) * SC_M;
            __half l = __float2half_rn(r2 * 4194304.0f);
            shi[p][c] = __half_as_ushort(h);
            smd[p][c] = __half_as_ushort(m);
            slo[p][c] = __half_as_ushort(l);
        }
        __syncthreads();
        int px = tid >> 2, part = tid & 3;
        size_t base = ((size_t)n*HWHW + pix0 + px)*32 + part*8;
        #pragma unroll
        for (int i = 0; i < 8; i++) {
            int c = part*16 + i*2;
            xhi [base+i] = (unsigned)shi[px][c] | ((unsigned)shi[px][c+1] << 16);
            xmid[base+i] = (unsigned)smd[px][c] | ((unsigned)smd[px][c+1] << 16);
            xlo [base+i] = (unsigned)slo[px][c] | ((unsigned)slo[px][c+1] << 16);
        }
    }
}

// ================= prep2: BN coefficients =================
__global__ void prep2_kernel(const float* __restrict__ g, const float* __restrict__ b,
                             const float* __restrict__ m, const float* __restrict__ v,
                             const float* __restrict__ wsc,
                             float* __restrict__ A, float* __restrict__ B,
                             float* __restrict__ inv4, float* __restrict__ bias4) {
    int i = threadIdx.x;   // 320
    float iv = g[i] * __fdiv_rn(1.0f, __fsqrt_rn(v[i] + 1e-5f));
    float bias = b[i] - m[i] * iv;
    if (i < 256) {
        int s = i >> 6;
        float a = wsc[i] * iv;
        if (s > 0) a *= R_S;
        A[i] = a;
        B[i] = bias;
    } else {
        inv4[i-256] = iv;
        bias4[i-256] = bias;
    }
}

// -------- 1x1 conv (downsample) + bn4 + qhtanh -> NHWC packed s8 ------
__global__ __launch_bounds__(256, 2)
void conv1x1_kernel(const float* __restrict__ x, const float* __restrict__ wt,
                    const float* __restrict__ bninv, const float* __restrict__ bnbias,
                    unsigned* __restrict__ out) {
    int b  = blockIdx.x;          // 784 = 16 * 49
    int n  = b / 49;
    int p0 = (b - n*49) * 256;
    __shared__ float xs[16][256];
    __shared__ __align__(8) float ws[16][64];
    __shared__ unsigned s_out[256][16];
    int t   = threadIdx.x;
    int pl  = t & 63;
    int cog = t >> 6;
    unsigned long long acc2[4][8];
    #pragma unroll
    for (int j = 0; j < 4; j++)
        #pragma unroll
        for (int k2 = 0; k2 < 8; k2++) acc2[j][k2] = 0ULL;

    const float* xN = x + (size_t)n*CC*HWHW + p0;
    for (int c0 = 0; c0 < CC; c0 += 16) {
        __syncthreads();
        #pragma unroll
        for (int r = 0; r < 16; r++) xs[r][t] = xN[(size_t)(c0+r)*HWHW + t];
        #pragma unroll
        for (int r = 0; r < 4; r++) {
            int e = t + r*256;
            ws[e>>6][e&63] = wt[(c0 + (e>>6))*64 + (e&63)];
        }
        __syncthreads();
        #pragma unroll
        for (int ci = 0; ci < 16; ci++) {
            unsigned long long w2[8];
            #pragma unroll
            for (int k2 = 0; k2 < 8; k2++)
                w2[k2] = *(const unsigned long long*)&ws[ci][cog*16 + 2*k2];
            #pragma unroll
            for (int j = 0; j < 4; j++) {
                unsigned long long xv2 = pack_dup(xs[ci][pl + 64*j]);
                #pragma unroll
                for (int k2 = 0; k2 < 8; k2++)
                    acc2[j][k2] = fma2(xv2, w2[k2], acc2[j][k2]);
            }
        }
    }
    #pragma unroll
    for (int j = 0; j < 4; j++) {
        unsigned words[4] = {0,0,0,0};
        #pragma unroll
        for (int k2 = 0; k2 < 8; k2++) {
            float a0, a1;
            unpack2(acc2[j][k2], a0, a1);
            #pragma unroll
            for (int h = 0; h < 2; h++) {
                int k = 2*k2 + h;
                int co = cog*16 + k;
                float v = fmaf(h ? a1 : a0, bninv[co], bnbias[co]);
                float c = fminf(fmaxf(v, -10.0f), 10.0f);
                float r = fminf(fmaxf(rintf(__fdiv_rn(c, HT_S)), -127.f), 127.f);
                words[k>>2] |= (((unsigned)(int)r) & 0xFFu) << (8*(k&3));
            }
        }
        #pragma unroll
        for (int q = 0; q < 4; q++) s_out[pl + 64*j][cog*4 + q] = words[q];
    }
    __syncthreads();
    uint4* gdst = (uint4*)(out + ((size_t)n*HWHW + p0 + t)*16);
    const uint4* srow = (const uint4*)&s_out[t][0];
    #pragma unroll
    for (int q = 0; q < 4; q++) gdst[q] = srow[q];
}

// ================ HMMA stage 0 (R12 config: 256 thr, 8x16 tile, ILP 1) ========
#define HPITCH_H 36
__global__ __launch_bounds__(256, 2)
void conv3x3_hmma0(const unsigned* __restrict__ xhi, const unsigned* __restrict__ xmid,
                   const unsigned* __restrict__ xlo,
                   const uint2* __restrict__ bfrag,
                   const float* __restrict__ Acoef, const float* __restrict__ Bcoef,
                   unsigned* __restrict__ outp) {
    extern __shared__ char dsm[];
    uint2* sBf = (uint2*)dsm;
    unsigned* halo = (unsigned*)(dsm + 73728);
    __shared__ float sAc[64], sBc[64];

    int tid = threadIdx.x;
    int wid = tid >> 5;
    int lane = tid & 31;
    int n  = blockIdx.z;
    int h0 = blockIdx.y * 8;
    int w0 = blockIdx.x * 16;

    if (tid < 64) { sAc[tid] = Acoef[tid]; sBc[tid] = Bcoef[tid]; }
    {
        const uint4* src = (const uint4*)bfrag;
        uint4* dst = (uint4*)sBf;
        #pragma unroll
        for (int i = 0; i < 18; i++) dst[tid + i*256] = src[tid + i*256];
    }
    unsigned haloAddr = smem_u32(halo);
    unsigned aBase = haloAddr + (unsigned)((wid*18 + (lane & 15))*144 + (lane >> 4)*16);

    float acc[8][4];
    #pragma unroll
    for (int nt = 0; nt < 8; nt++)
        #pragma unroll
        for (int q = 0; q < 4; q++) acc[nt][q] = 0.f;

    #pragma unroll 1
    for (int pass = 0; pass < 3; pass++) {
        const unsigned* xsrc = (pass == 0) ? xlo : (pass == 1) ? xmid : xhi;
        __syncthreads();
        for (int e = tid; e < 5760; e += 256) {
            int r = e / 576, rr = e % 576, c = rr >> 5, q = rr & 31;
            int hh = h0 - 1 + r, ww = w0 - 1 + c;
            unsigned v = 0;
            if ((unsigned)hh < HH && (unsigned)ww < WW)
                v = xsrc[((size_t)n*HWHW + (size_t)hh*WW + ww)*32 + q];
            halo[(r*18 + c)*HPITCH_H + q] = v;
        }
        __syncthreads();
        #pragma unroll 1
        for (int dy = 0; dy < 3; dy++)
        #pragma unroll
        for (int dx = 0; dx < 3; dx++) {
            unsigned rowOff = aBase + (unsigned)((dy*18 + dx)*144);
            #pragma unroll
            for (int c = 0; c < 4; c++) {
                unsigned a0, a1, a2, a3;
                ldsm_x4(a0, a1, a2, a3, rowOff + c*32);
                const uint2* bp = sBf + ((dy*3 + dx)*4 + c)*256 + lane;
                #pragma unroll
                for (int nt = 0; nt < 8; nt++) {
                    uint2 b = bp[nt*32];
                    mma_f16(acc[nt], a0, a1, a2, a3, b.x, b.y);
                }
            }
        }
        if (pass < 2) {
            #pragma unroll
            for (int nt = 0; nt < 8; nt++)
                #pragma unroll
                for (int q = 0; q < 4; q++) acc[nt][q] *= SC_M;
        }
    }

    unsigned short pairs[2][8];
    #pragma unroll
    for (int h2 = 0; h2 < 2; h2++) {
        int px = (lane >> 2) + 8*h2;
        size_t gw = ((size_t)n*HWHW + (size_t)(h0 + wid)*WW + (w0 + px))*32 + (lane & 3);
        #pragma unroll
        for (int nt = 0; nt < 8; nt++) {
            unsigned wh = __ldg(xhi  + gw + nt*4);
            unsigned wm = __ldg(xmid + gw + nt*4);
            unsigned wl = __ldg(xlo  + gw + nt*4);
            unsigned pr = 0;
            #pragma unroll
            for (int j = 0; j < 2; j++) {
                int co = nt*8 + (lane & 3)*2 + j;
                float v = fmaf(acc[nt][2*h2 + j], sAc[co], sBc[co]);
                __half xh = __ushort_as_half((unsigned short)((wh >> (16*j)) & 0xFFFF));
                __half xm = __ushort_as_half((unsigned short)((wm >> (16*j)) & 0xFFFF));
                __half xl = __ushort_as_half((unsigned short)((wl >> (16*j)) & 0xFFFF));
                float xv = (__half2float(xh) + __half2float(xm) * SC_M)
                         + __half2float(xl) * SC_L;
                float r = qhtanh_f(v) + qhtanh_f(xv);
                pr |= qrelu_code(r) << (8*j);
            }
            pairs[h2][nt] = (unsigned short)pr;
        }
    }
    __syncthreads();
    unsigned short* stag = (unsigned short*)halo;
    #pragma unroll
    for (int h2 = 0; h2 < 2; h2++) {
        int px = (lane >> 2) + 8*h2;
        int pxl = wid*16 + px;
        #pragma unroll
        for (int nt = 0; nt < 8; nt++)
            stag[pxl*32 + nt*4 + (lane & 3)] = pairs[h2][nt];
    }
    __syncthreads();
    {
        int pxl = tid >> 1, half = tid & 1;
        int h = h0 + (pxl >> 4), w = w0 + (pxl & 15);
        const uint4* src = (const uint4*)((char*)halo + pxl*64 + half*32);
        uint4* dst = (uint4*)(outp + ((size_t)n*HWHW + (size_t)h*WW + w)*16 + half*8);
        dst[0] = src[0];
        dst[1] = src[1];
    }
}

// ================ IMMA int stages: 16x16 tile, 256 thr, M=32/warp ============
// 8 warps; warp w owns h-rows 2w, 2w+1. B LDS amortized over 2 MMAs; ILP 2.
// smem: sB uint2[4608] (36864B) | halo u32[324 px][20] (25920B) => 62784B, 2 CTAs/SM
#define HPITCH_I 20
template<int EPI>
__global__ __launch_bounds__(256, 2)
void conv3x3_imma(const unsigned* __restrict__ act_in, const uint2* __restrict__ bfrag,
                  const float* __restrict__ Acoef, const float* __restrict__ Bcoef,
                  const unsigned* __restrict__ e1, unsigned* __restrict__ outp) {
    extern __shared__ char dsm[];
    uint2* sBf = (uint2*)dsm;
    unsigned* halo = (unsigned*)(dsm + 36864);
    __shared__ float sAc[64], sBc[64];

    int tid = threadIdx.x;
    int wid = tid >> 5;          // 0..7
    int lane = tid & 31;
    int n  = blockIdx.z;
    int h0 = blockIdx.y * 16;
    int w0 = blockIdx.x * 16;

    if (tid < 64) { sAc[tid] = Acoef[tid]; sBc[tid] = Bcoef[tid]; }
    {
        const uint4* src = (const uint4*)bfrag;
        uint4* dst = (uint4*)sBf;
        #pragma unroll
        for (int i = 0; i < 9; i++) dst[tid + i*256] = src[tid + i*256];
    }
    const unsigned* inN = act_in + (size_t)n*HWHW*16;
    for (int e = tid; e < 5184; e += 256) {          // 18 rows x 18 cols x 16 words
        int r = e / 288, rr = e % 288, c = rr >> 4, q = rr & 15;
        int hh = h0 - 1 + r, ww = w0 - 1 + c;
        unsigned v = 0;
        if ((unsigned)hh < HH && (unsigned)ww < WW)
            v = inN[((size_t)hh*WW + ww)*16 + q];
        halo[(r*18 + c)*HPITCH_I + q] = v;
    }
    __syncthreads();

    unsigned haloAddr = smem_u32(halo);
    unsigned aBase0 = haloAddr + (unsigned)(((wid*2)*18 + (lane & 15))*80 + (lane >> 4)*16);
    unsigned aBase1 = aBase0 + 18*80;

    int acc[2][8][4];
    #pragma unroll
    for (int hr = 0; hr < 2; hr++)
        #pragma unroll
        for (int nt = 0; nt < 8; nt++)
            #pragma unroll
            for (int q = 0; q < 4; q++) acc[hr][nt][q] = 0;

    #pragma unroll 1
    for (int dy = 0; dy < 3; dy++)
    #pragma unroll
    for (int dx = 0; dx < 3; dx++) {
        unsigned off = (unsigned)((dy*18 + dx)*80);
        #pragma unroll
        for (int c = 0; c < 2; c++) {
            unsigned a0, a1, a2, a3, b0, b1, b2, b3;
            ldsm_x4(a0, a1, a2, a3, aBase0 + off + c*32);
            ldsm_x4(b0, b1, b2, b3, aBase1 + off + c*32);
            const uint2* bp = sBf + ((dy*3 + dx)*2 + c)*256 + lane;
            #pragma unroll
            for (int nt = 0; nt < 8; nt++) {
                uint2 b = bp[nt*32];
                mma_s8(acc[0][nt], a0, a1, a2, a3, b.x, b.y);
                mma_s8(acc[1][nt], b0, b1, b2, b3, b.x, b.y);
            }
        }
    }

    // epilogue -> u8 code pairs
    unsigned short pairs[2][2][8];
    #pragma unroll
    for (int hr = 0; hr < 2; hr++) {
        int hrow = wid*2 + hr;
        int ctr_row = (hrow + 1)*18;
        #pragma unroll
        for (int h2 = 0; h2 < 2; h2++) {
            int px = (lane >> 2) + 8*h2;
            int ctr = (ctr_row + px + 1)*HPITCH_I;
            size_t pixw = ((size_t)n*HWHW + (size_t)(h0 + hrow)*WW + (w0 + px))*16;
            int wsel = (lane & 3) >> 1;
            int b0 = ((lane & 3) & 1)*2;
            #pragma unroll
            for (int nt = 0; nt < 8; nt++) {
                unsigned inw = halo[ctr + 2*nt + wsel];
                unsigned ew = 0;
                if (EPI == 1 || EPI == 3) ew = e1[pixw + 2*nt + wsel];
                unsigned pr = 0;
                #pragma unroll
                for (int j = 0; j < 2; j++) {
                    int co = nt*8 + (lane & 3)*2 + j;
                    float v = fmaf((float)acc[hr][nt][2*h2 + j], sAc[co], sBc[co]);
                    int byte = b0 + j;
                    float in_val = (float)((inw >> (8*byte)) & 255u) * R_S;
                    float r;
                    if (EPI == 0) {
                        r = qhtanh_f(v) + qhtanh_f(in_val);
                    } else if (EPI == 1) {
                        int ec = (int)(ew << (24 - 8*byte)) >> 24;
                        float tq = qhtanh_f(v) + (float)ec * HT_S;
                        r = qhtanh_f(tq) + qhtanh_f(in_val);
                    } else {
                        float ev = (float)((ew >> (8*byte)) & 255u) * R_S;
                        float tq = qhtanh_f(v) + qhtanh_f(ev);
                        r = qhtanh_f(in_val) + qhtanh_f(tq);
                    }
                    pr |= qrelu_code(r) << (8*j);
                }
                pairs[hr][h2][nt] = (unsigned short)pr;
            }
        }
    }
    __syncthreads();                       // all halo reads done; reuse as staging
    unsigned short* stag = (unsigned short*)halo;
    #pragma unroll
    for (int hr = 0; hr < 2; hr++)
        #pragma unroll
        for (int h2 = 0; h2 < 2; h2++) {
            int px = (lane >> 2) + 8*h2;
            int pxl = (wid*2 + hr)*16 + px;
            #pragma unroll
            for (int nt = 0; nt < 8; nt++)
                stag[pxl*32 + nt*4 + (lane & 3)] = pairs[hr][h2][nt];
        }
    __syncthreads();
    {
        int pxl = tid;                  // 256 px, one per thread
        int h = h0 + (pxl >> 4), w = w0 + (pxl & 15);
        const uint4* src = (const uint4*)((char*)halo + pxl*64);
        uint4* dst = (uint4*)(outp + ((size_t)n*HWHW + (size_t)h*WW + w)*16);
        #pragma unroll
        for (int q = 0; q < 4; q++) dst[q] = src[q];
    }
}

// -------- final: u8 NHWC codes -> fp32 NCHW (out = code * R_S) --------
__global__ void out_expand_kernel(const unsigned* __restrict__ codes,
                                  float* __restrict__ out) {
    __shared__ unsigned st[64][17];
    int blk = blockIdx.x;             // 16*196
    int n = blk / 196;
    int pix0 = (blk % 196) * 64;
    int tid = threadIdx.x;
    #pragma unroll
    for (int i = 0; i < 4; i++) {
        int e = tid + i*256;
        int px = e >> 4, q = e & 15;
        st[px][q] = codes[((size_t)n*HWHW + pix0 + px)*16 + q];
    }
    __syncthreads();
    int c = tid >> 2, qq = tid & 3;
    float* dst = out + ((size_t)n*64 + c)*HWHW + pix0 + qq*16;
    #pragma unroll
    for (int i = 0; i < 16; i++) {
        unsigned w = st[qq*16 + i][c >> 2];
        dst[i] = (float)((w >> (8*(c & 3))) & 255u) * R_S;
    }
}

// -------------------- host launcher --------------------------------
extern "C" void kernel_launch(void* const* d_in, const int* in_sizes, int n_in,
                              void* d_out, int out_size) {
    const float* x      = (const float*)d_in[0];
    const float* conv_w = (const float*)d_in[1];
    const float* ds_w   = (const float*)d_in[2];
    const float* bng    = (const float*)d_in[3];
    const float* bnb    = (const float*)d_in[4];
    const float* bnm    = (const float*)d_in[5];
    const float* bnvv   = (const float*)d_in[6];
    float* out = (float*)d_out;

    unsigned *act1, *act2, *act3, *act4, *idq, *xhi, *xmid, *xlo;
    uint2 *bfi, *bfh;
    float *dsq, *wsc, *A, *B, *inv4, *bias4;
    cudaGetSymbolAddress((void**)&act1, g_act1);
    cudaGetSymbolAddress((void**)&act2, g_act2);
    cudaGetSymbolAddress((void**)&act3, g_act3);
    cudaGetSymbolAddress((void**)&act4, g_act4);
    cudaGetSymbolAddress((void**)&idq,  g_idq);
    cudaGetSymbolAddress((void**)&xhi,  g_xhi);
    cudaGetSymbolAddress((void**)&xmid, g_xmid);
    cudaGetSymbolAddress((void**)&xlo,  g_xlo);
    cudaGetSymbolAddress((void**)&bfi,  g_bfi);
    cudaGetSymbolAddress((void**)&bfh,  g_bfh);
    cudaGetSymbolAddress((void**)&dsq,  g_dsq);
    cudaGetSymbolAddress((void**)&wsc,  g_wsc);
    cudaGetSymbolAddress((void**)&A,    g_A);
    cudaGetSymbolAddress((void**)&B,    g_B);
    cudaGetSymbolAddress((void**)&inv4, g_bninv4);
    cudaGetSymbolAddress((void**)&bias4,g_bnbias4);

    const int SMEMI = 36864 + 25920;            // 62,784 -> 2 CTAs/SM
    const int SMEM0 = 73728 + 25920;            // 99,648 -> 2 CTAs/SM
    cudaFuncSetAttribute(conv3x3_hmma0,   cudaFuncAttributeMaxDynamicSharedMemorySize, SMEM0);
    cudaFuncSetAttribute(conv3x3_imma<0>, cudaFuncAttributeMaxDynamicSharedMemorySize, SMEMI);
    cudaFuncSetAttribute(conv3x3_imma<1>, cudaFuncAttributeMaxDynamicSharedMemorySize, SMEMI);
    cudaFuncSetAttribute(conv3x3_imma<3>, cudaFuncAttributeMaxDynamicSharedMemorySize, SMEMI);

    prep1_kernel<<<PREP1_GRID, 256>>>(conv_w, ds_w, x, wsc, bfi, bfh, dsq, xhi, xmid, xlo);
    prep2_kernel<<<1, 320>>>(bng, bnb, bnm, bnvv, wsc, A, B, inv4, bias4);
    conv1x1_kernel<<<784, 256>>>(x, dsq, inv4, bias4, idq);

    dim3 grid0(7, 14, NN);   // hmma0: 16w x 8h tiles
    dim3 gridI(7, 7,  NN);   // imma: 16w x 16h tiles
    conv3x3_hmma0<<<grid0, 256, SMEM0>>>(xhi, xmid, xlo, bfh, A + 0*CC, B + 0*CC, act1);
    conv3x3_imma<1><<<gridI, 256, SMEMI>>>(act1, bfi + 0*4608, A + 1*CC, B + 1*CC, idq,  act2);
    conv3x3_imma<0><<<gridI, 256, SMEMI>>>(act2, bfi + 1*4608, A + 2*CC, B + 2*CC, nullptr, act3);
    conv3x3_imma<3><<<gridI, 256, SMEMI>>>(act3, bfi + 2*4608, A + 3*CC, B + 3*CC, act2, act4);
    out_expand_kernel<<<16*196, 256>>>(act4, out);
}

// round 15
// speedup vs baseline: 1.2193x; 1.1496x over previous
#include <cuda_runtime.h>
#include <cuda_fp16.h>

#define NN 16
#define CC 64
#define HH 112
#define WW 112
#define HWHW (HH*WW)               // 12544
#define PKW (NN*16*HWHW)           // u8-packed NHWC act words
#define XHW (NN*HWHW*32)           // f16-packed x words (hi/mid/lo)

#define R_S  (10.0f/255.0f)
#define HT_S (10.0f/127.0f)
#define SC_M (1.0f/2048.0f)        // 2^-11
#define SC_L (1.0f/4194304.0f)     // 2^-22

// -------- device scratch ----------
__device__ unsigned g_act1[PKW];
__device__ unsigned g_act2[PKW];
__device__ unsigned g_act3[PKW];
__device__ unsigned g_act4[PKW];
__device__ unsigned g_idq [PKW];
__device__ unsigned g_xhi [XHW];
__device__ unsigned g_xmid[XHW];
__device__ unsigned g_xlo [XHW];
__device__ __align__(16) uint2 g_bfh[4*9*4*8*32];   // f16 B fragments, all 4 stages
__device__ float    g_dsq [CC*CC];
__device__ float    g_wsc [4*CC];
__device__ float    g_cs  [4*CC];      // 1024 * signed colsum
__device__ float    g_A   [4*CC];
__device__ float    g_B   [4*CC];
__device__ float    g_bninv4 [CC];
__device__ float    g_bnbias4[CC];

// ================= helpers =================
__device__ __forceinline__ unsigned smem_u32(const void* p) {
    unsigned a;
    asm("{ .reg .u64 t; cvta.to.shared.u64 t, %1; cvt.u32.u64 %0, t; }" : "=r"(a) : "l"(p));
    return a;
}
__device__ __forceinline__ void ldsm_x4(unsigned& r0, unsigned& r1, unsigned& r2,
                                        unsigned& r3, unsigned addr) {
    asm volatile("ldmatrix.sync.aligned.m8n8.x4.shared.b16 {%0,%1,%2,%3}, [%4];"
        : "=r"(r0), "=r"(r1), "=r"(r2), "=r"(r3) : "r"(addr));
}
__device__ __forceinline__ void mma_f16(float* d, unsigned a0, unsigned a1, unsigned a2,
                                        unsigned a3, unsigned b0, unsigned b1) {
    asm volatile("mma.sync.aligned.m16n8k16.row.col.f32.f16.f16.f32 "
        "{%0,%1,%2,%3}, {%4,%5,%6,%7}, {%8,%9}, {%0,%1,%2,%3};"
        : "+f"(d[0]), "+f"(d[1]), "+f"(d[2]), "+f"(d[3])
        : "r"(a0), "r"(a1), "r"(a2), "r"(a3), "r"(b0), "r"(b1));
}
__device__ __forceinline__ unsigned prmt64(unsigned a, unsigned sel) {
    unsigned d, c = 0x64646464u;
    asm("prmt.b32 %0, %1, %2, %3;" : "=r"(d) : "r"(a), "r"(c), "r"(sel));
    return d;
}

// ================= quantizers (round-half-even, match jnp) =================
__device__ __forceinline__ float qhtanh_f(float x) {
    float c = fminf(fmaxf(x, -10.0f), 10.0f);
    float r = rintf(__fdiv_rn(c, HT_S));
    r = fminf(fmaxf(r, -127.0f), 127.0f);
    return r * HT_S;
}
__device__ __forceinline__ unsigned qrelu_code(float x) {
    float c = fminf(fmaxf(x, 0.0f), 10.0f);
    float r = rintf(__fdiv_rn(c, R_S));
    return (unsigned)(int)fminf(r, 255.0f);
}
__device__ __forceinline__ unsigned long long pack_dup(float v) {
    unsigned long long r;
    asm("mov.b64 %0, {%1, %1};" : "=l"(r) : "f"(v));
    return r;
}
__device__ __forceinline__ unsigned long long fma2(unsigned long long a, unsigned long long b,
                                                   unsigned long long c) {
    unsigned long long d;
    asm("fma.rn.f32x2 %0, %1, %2, %3;" : "=l"(d) : "l"(a), "l"(b), "l"(c));
    return d;
}
__device__ __forceinline__ void unpack2(unsigned long long v, float& lo, float& hi) {
    asm("mov.b64 {%0, %1}, %2;" : "=f"(lo), "=f"(hi) : "l"(v));
}

// ================= prep1: fused weight prep + x transpose (block roles) ======
// [0,256)      : binary weight per-channel scale + 1024*colsum
// [256,400)    : f16 B fragments, 4 stages (36864 elems)
// [400,464)    : int8 1x1 weight quant
// [464,3600)   : x NCHW fp32 -> NHWC f16 hi/mid/lo
#define PREP1_GRID 3600
__global__ void prep1_kernel(const float* __restrict__ w, const float* __restrict__ ds_w,
                             const float* __restrict__ x,
                             float* __restrict__ wsc, float* __restrict__ cs,
                             uint2* __restrict__ bfh, float* __restrict__ dsq,
                             unsigned* __restrict__ xhi, unsigned* __restrict__ xmid,
                             unsigned* __restrict__ xlo) {
    int b = blockIdx.x, tid = threadIdx.x;
    __shared__ float red[256], red2[256];
    __shared__ unsigned short shi[64][66], smd[64][66], slo[64][66];

    if (b < 256) {                              // ---- weight scale + colsum
        const float* wc = w + b*576;
        float s = 0.f, ss = 0.f;
        for (int e = tid; e < 576; e += 256) {
            float v = wc[e];
            s += fabsf(v);
            ss += (v >= 0.f) ? 1.f : -1.f;
        }
        red[tid] = s; red2[tid] = ss;
        __syncthreads();
        for (int off = 128; off > 0; off >>= 1) {
            if (tid < off) { red[tid] += red[tid+off]; red2[tid] += red2[tid+off]; }
            __syncthreads();
        }
        if (tid == 0) {
            wsc[b] = fmaxf(red[0] * (1.0f/576.0f), 2e-16f);
            cs[b]  = 1024.0f * red2[0];
        }
    } else if (b < 400) {                       // ---- f16 B fragments (4 stages)
        int idx = (b-256)*256 + tid;
        if (idx < 4*9216) {
            int s    = idx / 9216;
            int rem  = idx % 9216;
            int lane = rem & 31;
            int nt   = (rem >> 5) & 7;
            int c    = (rem >> 8) & 3;
            int tap  = rem >> 10;
            int co   = nt*8 + (lane >> 2);
            int ci   = c*16 + (lane & 3)*2;
            unsigned h00 = (w[((s*64+co)*64 + ci  )*9 + tap] >= 0.f) ? 0x3C00u : 0xBC00u;
            unsigned h01 = (w[((s*64+co)*64 + ci+1)*9 + tap] >= 0.f) ? 0x3C00u : 0xBC00u;
            unsigned h10 = (w[((s*64+co)*64 + ci+8)*9 + tap] >= 0.f) ? 0x3C00u : 0xBC00u;
            unsigned h11 = (w[((s*64+co)*64 + ci+9)*9 + tap] >= 0.f) ? 0x3C00u : 0xBC00u;
            bfh[idx] = make_uint2(h00 | (h01 << 16), h10 | (h11 << 16));
        }
    } else if (b < 464) {                       // ---- int8 1x1 quant
        int co = b - 400;
        red[tid] = (tid < 64) ? fabsf(ds_w[co*64 + tid]) : 0.f;
        __syncthreads();
        for (int off = 128; off > 0; off >>= 1) {
            if (tid < off) red[tid] = fmaxf(red[tid], red[tid+off]);
            __syncthreads();
        }
        if (tid < 64) {
            float scale = fmaxf(red[0], 2e-16f) / 127.0f;
            float q = fminf(fmaxf(rintf(__fdiv_rn(ds_w[co*64 + tid], scale)), -127.f), 127.f) * scale;
            dsq[tid*64 + co] = q;
        }
    } else {                                    // ---- transpose x -> hi/mid/lo
        int blk = b - 464;                      // 0..3135
        int n = blk / 196;
        int pix0 = (blk % 196) * 64;
        #pragma unroll
        for (int pass = 0; pass < 16; pass++) {
            int idx = tid + pass*256;
            int c = idx >> 6, p = idx & 63;
            float v = x[((size_t)n*64 + c)*HWHW + pix0 + p];
            __half h = __float2half_rn(v);
            float r1 = v - __half2float(h);
            __half m = __float2half_rn(r1 * 2048.0f);
            float r2 = r1 - __half2float(m) * SC_M;
            __half l = __float2half_rn(r2 * 4194304.0f);
            shi[p][c] = __half_as_ushort(h);
            smd[p][c] = __half_as_ushort(m);
            slo[p][c] = __half_as_ushort(l);
        }
        __syncthreads();
        int px = tid >> 2, part = tid & 3;
        size_t base = ((size_t)n*HWHW + pix0 + px)*32 + part*8;
        #pragma unroll
        for (int i = 0; i < 8; i++) {
            int c = part*16 + i*2;
            xhi [base+i] = (unsigned)shi[px][c] | ((unsigned)shi[px][c+1] << 16);
            xmid[base+i] = (unsigned)smd[px][c] | ((unsigned)smd[px][c+1] << 16);
            xlo [base+i] = (unsigned)slo[px][c] | ((unsigned)slo[px][c+1] << 16);
        }
    }
}

// ================= prep2: BN coefficients =================
__global__ void prep2_kernel(const float* __restrict__ g, const float* __restrict__ b,
                             const float* __restrict__ m, const float* __restrict__ v,
                             const float* __restrict__ wsc,
                             float* __restrict__ A, float* __restrict__ B,
                             float* __restrict__ inv4, float* __restrict__ bias4) {
    int i = threadIdx.x;   // 320
    float iv = g[i] * __fdiv_rn(1.0f, __fsqrt_rn(v[i] + 1e-5f));
    float bias = b[i] - m[i] * iv;
    if (i < 256) {
        int s = i >> 6;
        float a = wsc[i] * iv;
        if (s > 0) a *= R_S;
        A[i] = a;
        B[i] = bias;
    } else {
        inv4[i-256] = iv;
        bias4[i-256] = bias;
    }
}

// -------- 1x1 conv (downsample) + bn4 + qhtanh -> NHWC packed s8 ------
__global__ __launch_bounds__(256, 2)
void conv1x1_kernel(const float* __restrict__ x, const float* __restrict__ wt,
                    const float* __restrict__ bninv, const float* __restrict__ bnbias,
                    unsigned* __restrict__ out) {
    int b  = blockIdx.x;          // 784 = 16 * 49
    int n  = b / 49;
    int p0 = (b - n*49) * 256;
    __shared__ float xs[16][256];
    __shared__ __align__(8) float ws[16][64];
    __shared__ unsigned s_out[256][16];
    int t   = threadIdx.x;
    int pl  = t & 63;
    int cog = t >> 6;
    unsigned long long acc2[4][8];
    #pragma unroll
    for (int j = 0; j < 4; j++)
        #pragma unroll
        for (int k2 = 0; k2 < 8; k2++) acc2[j][k2] = 0ULL;

    const float* xN = x + (size_t)n*CC*HWHW + p0;
    for (int c0 = 0; c0 < CC; c0 += 16) {
        __syncthreads();
        #pragma unroll
        for (int r = 0; r < 16; r++) xs[r][t] = xN[(size_t)(c0+r)*HWHW + t];
        #pragma unroll
        for (int r = 0; r < 4; r++) {
            int e = t + r*256;
            ws[e>>6][e&63] = wt[(c0 + (e>>6))*64 + (e&63)];
        }
        __syncthreads();
        #pragma unroll
        for (int ci = 0; ci < 16; ci++) {
            unsigned long long w2[8];
            #pragma unroll
            for (int k2 = 0; k2 < 8; k2++)
                w2[k2] = *(const unsigned long long*)&ws[ci][cog*16 + 2*k2];
            #pragma unroll
            for (int j = 0; j < 4; j++) {
                unsigned long long xv2 = pack_dup(xs[ci][pl + 64*j]);
                #pragma unroll
                for (int k2 = 0; k2 < 8; k2++)
                    acc2[j][k2] = fma2(xv2, w2[k2], acc2[j][k2]);
            }
        }
    }
    #pragma unroll
    for (int j = 0; j < 4; j++) {
        unsigned words[4] = {0,0,0,0};
        #pragma unroll
        for (int k2 = 0; k2 < 8; k2++) {
            float a0, a1;
            unpack2(acc2[j][k2], a0, a1);
            #pragma unroll
            for (int h = 0; h < 2; h++) {
                int k = 2*k2 + h;
                int co = cog*16 + k;
                float v = fmaf(h ? a1 : a0, bninv[co], bnbias[co]);
                float c = fminf(fmaxf(v, -10.0f), 10.0f);
                float r = fminf(fmaxf(rintf(__fdiv_rn(c, HT_S)), -127.f), 127.f);
                words[k>>2] |= (((unsigned)(int)r) & 0xFFu) << (8*(k&3));
            }
        }
        #pragma unroll
        for (int q = 0; q < 4; q++) s_out[pl + 64*j][cog*4 + q] = words[q];
    }
    __syncthreads();
    uint4* gdst = (uint4*)(out + ((size_t)n*HWHW + p0 + t)*16);
    const uint4* srow = (const uint4*)&s_out[t][0];
    #pragma unroll
    for (int q = 0; q < 4; q++) gdst[q] = srow[q];
}

// ================ HMMA stage 0 (R12 config: 256 thr, 8x16 tile) ========
#define HPITCH_H 36
__global__ __launch_bounds__(256, 2)
void conv3x3_hmma0(const unsigned* __restrict__ xhi, const unsigned* __restrict__ xmid,
                   const unsigned* __restrict__ xlo,
                   const uint2* __restrict__ bfrag,
                   const float* __restrict__ Acoef, const float* __restrict__ Bcoef,
                   unsigned* __restrict__ outp) {
    extern __shared__ char dsm[];
    uint2* sBf = (uint2*)dsm;
    unsigned* halo = (unsigned*)(dsm + 73728);
    __shared__ float sAc[64], sBc[64];

    int tid = threadIdx.x;
    int wid = tid >> 5;
    int lane = tid & 31;
    int n  = blockIdx.z;
    int h0 = blockIdx.y * 8;
    int w0 = blockIdx.x * 16;

    if (tid < 64) { sAc[tid] = Acoef[tid]; sBc[tid] = Bcoef[tid]; }
    {
        const uint4* src = (const uint4*)bfrag;
        uint4* dst = (uint4*)sBf;
        #pragma unroll
        for (int i = 0; i < 18; i++) dst[tid + i*256] = src[tid + i*256];
    }
    unsigned haloAddr = smem_u32(halo);
    unsigned aBase = haloAddr + (unsigned)((wid*18 + (lane & 15))*144 + (lane >> 4)*16);

    float acc[8][4];
    #pragma unroll
    for (int nt = 0; nt < 8; nt++)
        #pragma unroll
        for (int q = 0; q < 4; q++) acc[nt][q] = 0.f;

    #pragma unroll 1
    for (int pass = 0; pass < 3; pass++) {
        const unsigned* xsrc = (pass == 0) ? xlo : (pass == 1) ? xmid : xhi;
        __syncthreads();
        for (int e = tid; e < 5760; e += 256) {
            int r = e / 576, rr = e % 576, c = rr >> 5, q = rr & 31;
            int hh = h0 - 1 + r, ww = w0 - 1 + c;
            unsigned v = 0;
            if ((unsigned)hh < HH && (unsigned)ww < WW)
                v = xsrc[((size_t)n*HWHW + (size_t)hh*WW + ww)*32 + q];
            halo[(r*18 + c)*HPITCH_H + q] = v;
        }
        __syncthreads();
        #pragma unroll 1
        for (int dy = 0; dy < 3; dy++)
        #pragma unroll
        for (int dx = 0; dx < 3; dx++) {
            unsigned rowOff = aBase + (unsigned)((dy*18 + dx)*144);
            #pragma unroll
            for (int c = 0; c < 4; c++) {
                unsigned a0, a1, a2, a3;
                ldsm_x4(a0, a1, a2, a3, rowOff + c*32);
                const uint2* bp = sBf + ((dy*3 + dx)*4 + c)*256 + lane;
                #pragma unroll
                for (int nt = 0; nt < 8; nt++) {
                    uint2 b = bp[nt*32];
                    mma_f16(acc[nt], a0, a1, a2, a3, b.x, b.y);
                }
            }
        }
        if (pass < 2) {
            #pragma unroll
            for (int nt = 0; nt < 8; nt++)
                #pragma unroll
                for (int q = 0; q < 4; q++) acc[nt][q] *= SC_M;
        }
    }

    unsigned short pairs[2][8];
    #pragma unroll
    for (int h2 = 0; h2 < 2; h2++) {
        int px = (lane >> 2) + 8*h2;
        size_t gw = ((size_t)n*HWHW + (size_t)(h0 + wid)*WW + (w0 + px))*32 + (lane & 3);
        #pragma unroll
        for (int nt = 0; nt < 8; nt++) {
            unsigned wh = __ldg(xhi  + gw + nt*4);
            unsigned wm = __ldg(xmid + gw + nt*4);
            unsigned wl = __ldg(xlo  + gw + nt*4);
            unsigned pr = 0;
            #pragma unroll
            for (int j = 0; j < 2; j++) {
                int co = nt*8 + (lane & 3)*2 + j;
                float v = fmaf(acc[nt][2*h2 + j], sAc[co], sBc[co]);
                __half xh = __ushort_as_half((unsigned short)((wh >> (16*j)) & 0xFFFF));
                __half xm = __ushort_as_half((unsigned short)((wm >> (16*j)) & 0xFFFF));
                __half xl = __ushort_as_half((unsigned short)((wl >> (16*j)) & 0xFFFF));
                float xv = (__half2float(xh) + __half2float(xm) * SC_M)
                         + __half2float(xl) * SC_L;
                float r = qhtanh_f(v) + qhtanh_f(xv);
                pr |= qrelu_code(r) << (8*j);
            }
            pairs[h2][nt] = (unsigned short)pr;
        }
    }
    __syncthreads();
    unsigned short* stag = (unsigned short*)halo;
    #pragma unroll
    for (int h2 = 0; h2 < 2; h2++) {
        int px = (lane >> 2) + 8*h2;
        int pxl = wid*16 + px;
        #pragma unroll
        for (int nt = 0; nt < 8; nt++)
            stag[pxl*32 + nt*4 + (lane & 3)] = pairs[h2][nt];
    }
    __syncthreads();
    {
        int pxl = tid >> 1, half = tid & 1;
        int h = h0 + (pxl >> 4), w = w0 + (pxl & 15);
        const uint4* src = (const uint4*)((char*)halo + pxl*64 + half*32);
        uint4* dst = (uint4*)(outp + ((size_t)n*HWHW + (size_t)h*WW + w)*16 + half*8);
        dst[0] = src[0];
        dst[1] = src[1];
    }
}

// ================ int stages via f16 HMMA (exact; EPI 0/1/3) ================
// halo holds f16(1024+code) pairs, layout identical to hmma0 (pitch 36 u32).
// D = sum(+-(1024+a)) = sum(+-a) + 1024*colsum; epilogue subtracts cs (exact ints).
// smem: sB uint2[9216] (73728B) | halo u32[180][36] (25920B) => 99648B, 2 CTAs/SM
template<int EPI>
__global__ __launch_bounds__(256, 2)
void conv3x3_hint(const unsigned* __restrict__ act_in, const uint2* __restrict__ bfrag,
                  const float* __restrict__ Acoef, const float* __restrict__ Bcoef,
                  const float* __restrict__ cs1024,
                  const unsigned* __restrict__ e1, unsigned* __restrict__ outp) {
    extern __shared__ char dsm[];
    uint2* sBf = (uint2*)dsm;
    unsigned* halo = (unsigned*)(dsm + 73728);
    __shared__ float sAc[64], sBc[64], sCs[64];

    int tid = threadIdx.x;
    int wid = tid >> 5;
    int lane = tid & 31;
    int n  = blockIdx.z;
    int h0 = blockIdx.y * 8;
    int w0 = blockIdx.x * 16;

    if (tid < 64) { sAc[tid] = Acoef[tid]; sBc[tid] = Bcoef[tid]; sCs[tid] = cs1024[tid]; }
    {
        const uint4* src = (const uint4*)bfrag;
        uint4* dst = (uint4*)sBf;
        #pragma unroll
        for (int i = 0; i < 18; i++) dst[tid + i*256] = src[tid + i*256];
    }
    // halo fill with u8 -> f16(1024+code) via prmt; OOB word 0 -> f16(1024) = code 0
    const unsigned* inN = act_in + (size_t)n*HWHW*16;
    for (int e = tid; e < 720; e += 256) {          // 180 px x 4 quarter-words
        int px = e >> 2, part = e & 3;
        int r = px / 18, c = px - r*18;
        int hh = h0 - 1 + r, ww = w0 - 1 + c;
        uint4 v = make_uint4(0,0,0,0);
        if ((unsigned)hh < HH && (unsigned)ww < WW)
            v = *(const uint4*)(inN + ((size_t)hh*WW + ww)*16 + part*4);
        unsigned* dst = halo + (r*18 + c)*HPITCH_H + part*8;
        dst[0] = prmt64(v.x, 0x4140u); dst[1] = prmt64(v.x, 0x4342u);
        dst[2] = prmt64(v.y, 0x4140u); dst[3] = prmt64(v.y, 0x4342u);
        dst[4] = prmt64(v.z, 0x4140u); dst[5] = prmt64(v.z, 0x4342u);
        dst[6] = prmt64(v.w, 0x4140u); dst[7] = prmt64(v.w, 0x4342u);
    }
    __syncthreads();

    unsigned haloAddr = smem_u32(halo);
    unsigned aBase = haloAddr + (unsigned)((wid*18 + (lane & 15))*144 + (lane >> 4)*16);

    float acc[8][4];
    #pragma unroll
    for (int nt = 0; nt < 8; nt++)
        #pragma unroll
        for (int q = 0; q < 4; q++) acc[nt][q] = 0.f;

    #pragma unroll 1
    for (int dy = 0; dy < 3; dy++)
    #pragma unroll
    for (int dx = 0; dx < 3; dx++) {
        unsigned rowOff = aBase + (unsigned)((dy*18 + dx)*144);
        #pragma unroll
        for (int c = 0; c < 4; c++) {
            unsigned a0, a1, a2, a3;
            ldsm_x4(a0, a1, a2, a3, rowOff + c*32);
            const uint2* bp = sBf + ((dy*3 + dx)*4 + c)*256 + lane;
            #pragma unroll
            for (int nt = 0; nt < 8; nt++) {
                uint2 b = bp[nt*32];
                mma_f16(acc[nt], a0, a1, a2, a3, b.x, b.y);
            }
        }
    }

    // epilogue: D -> subtract 1024*colsum (exact), residual 'in' from halo center
    unsigned short pairs[2][8];
    #pragma unroll
    for (int h2 = 0; h2 < 2; h2++) {
        int px = (lane >> 2) + 8*h2;
        int ctr = ((wid + 1)*18 + (px + 1))*HPITCH_H;
        size_t pixw = ((size_t)n*HWHW + (size_t)(h0 + wid)*WW + (w0 + px))*16;
        int wsel = (lane & 3) >> 1;
        int b0 = ((lane & 3) & 1)*2;
        #pragma unroll
        for (int nt = 0; nt < 8; nt++) {
            unsigned inw = halo[ctr + nt*4 + (lane & 3)];      // f16(1024+code) pair
            unsigned ew = 0;
            if (EPI == 1 || EPI == 3) ew = e1[pixw + 2*nt + wsel];
            unsigned pr = 0;
            #pragma unroll
            for (int j = 0; j < 2; j++) {
                int co = nt*8 + (lane & 3)*2 + j;
                float D = acc[nt][2*h2 + j] - sCs[co];
                float v = fmaf(D, sAc[co], sBc[co]);
                __half hv = __ushort_as_half((unsigned short)((inw >> (16*j)) & 0xFFFF));
                float in_val = (__half2float(hv) - 1024.0f) * R_S;
                float r;
                if (EPI == 0) {
                    r = qhtanh_f(v) + qhtanh_f(in_val);
                } else if (EPI == 1) {
                    int ec = (int)(ew << (24 - 8*(b0 + j))) >> 24;
                    float tq = qhtanh_f(v) + (float)ec * HT_S;
                    r = qhtanh_f(tq) + qhtanh_f(in_val);
                } else {
                    float ev = (float)((ew >> (8*(b0 + j))) & 255u) * R_S;
                    float tq = qhtanh_f(v) + qhtanh_f(ev);
                    r = qhtanh_f(in_val) + qhtanh_f(tq);
                }
                pr |= qrelu_code(r) << (8*j);
            }
            pairs[h2][nt] = (unsigned short)pr;
        }
    }
    __syncthreads();
    unsigned short* stag = (unsigned short*)halo;
    #pragma unroll
    for (int h2 = 0; h2 < 2; h2++) {
        int px = (lane >> 2) + 8*h2;
        int pxl = wid*16 + px;
        #pragma unroll
        for (int nt = 0; nt < 8; nt++)
            stag[pxl*32 + nt*4 + (lane & 3)] = pairs[h2][nt];
    }
    __syncthreads();
    {
        int pxl = tid >> 1, half = tid & 1;
        int h = h0 + (pxl >> 4), w = w0 + (pxl & 15);
        const uint4* src = (const uint4*)((char*)halo + pxl*64 + half*32);
        uint4* dst = (uint4*)(outp + ((size_t)n*HWHW + (size_t)h*WW + w)*16 + half*8);
        dst[0] = src[0];
        dst[1] = src[1];
    }
}

// -------- final: u8 NHWC codes -> fp32 NCHW (out = code * R_S) --------
__global__ void out_expand_kernel(const unsigned* __restrict__ codes,
                                  float* __restrict__ out) {
    __shared__ unsigned st[64][17];
    int blk = blockIdx.x;             // 16*196
    int n = blk / 196;
    int pix0 = (blk % 196) * 64;
    int tid = threadIdx.x;
    #pragma unroll
    for (int i = 0; i < 4; i++) {
        int e = tid + i*256;
        int px = e >> 4, q = e & 15;
        st[px][q] = codes[((size_t)n*HWHW + pix0 + px)*16 + q];
    }
    __syncthreads();
    int c = tid >> 2, qq = tid & 3;
    float* dst = out + ((size_t)n*64 + c)*HWHW + pix0 + qq*16;
    #pragma unroll
    for (int i = 0; i < 16; i++) {
        unsigned w = st[qq*16 + i][c >> 2];
        dst[i] = (float)((w >> (8*(c & 3))) & 255u) * R_S;
    }
}

// -------------------- host launcher --------------------------------
extern "C" void kernel_launch(void* const* d_in, const int* in_sizes, int n_in,
                              void* d_out, int out_size) {
    const float* x      = (const float*)d_in[0];
    const float* conv_w = (const float*)d_in[1];
    const float* ds_w   = (const float*)d_in[2];
    const float* bng    = (const float*)d_in[3];
    const float* bnb    = (const float*)d_in[4];
    const float* bnm    = (const float*)d_in[5];
    const float* bnvv   = (const float*)d_in[6];
    float* out = (float*)d_out;

    unsigned *act1, *act2, *act3, *act4, *idq, *xhi, *xmid, *xlo;
    uint2 *bfh;
    float *dsq, *wsc, *cs, *A, *B, *inv4, *bias4;
    cudaGetSymbolAddress((void**)&act1, g_act1);
    cudaGetSymbolAddress((void**)&act2, g_act2);
    cudaGetSymbolAddress((void**)&act3, g_act3);
    cudaGetSymbolAddress((void**)&act4, g_act4);
    cudaGetSymbolAddress((void**)&idq,  g_idq);
    cudaGetSymbolAddress((void**)&xhi,  g_xhi);
    cudaGetSymbolAddress((void**)&xmid, g_xmid);
    cudaGetSymbolAddress((void**)&xlo,  g_xlo);
    cudaGetSymbolAddress((void**)&bfh,  g_bfh);
    cudaGetSymbolAddress((void**)&dsq,  g_dsq);
    cudaGetSymbolAddress((void**)&wsc,  g_wsc);
    cudaGetSymbolAddress((void**)&cs,   g_cs);
    cudaGetSymbolAddress((void**)&A,    g_A);
    cudaGetSymbolAddress((void**)&B,    g_B);
    cudaGetSymbolAddress((void**)&inv4, g_bninv4);
    cudaGetSymbolAddress((void**)&bias4,g_bnbias4);

    const int SMEM0 = 73728 + 25920;            // 99,648 -> 2 CTAs/SM
    cudaFuncSetAttribute(conv3x3_hmma0,   cudaFuncAttributeMaxDynamicSharedMemorySize, SMEM0);
    cudaFuncSetAttribute(conv3x3_hint<0>, cudaFuncAttributeMaxDynamicSharedMemorySize, SMEM0);
    cudaFuncSetAttribute(conv3x3_hint<1>, cudaFuncAttributeMaxDynamicSharedMemorySize, SMEM0);
    cudaFuncSetAttribute(conv3x3_hint<3>, cudaFuncAttributeMaxDynamicSharedMemorySize, SMEM0);

    prep1_kernel<<<PREP1_GRID, 256>>>(conv_w, ds_w, x, wsc, cs, bfh, dsq, xhi, xmid, xlo);
    prep2_kernel<<<1, 320>>>(bng, bnb, bnm, bnvv, wsc, A, B, inv4, bias4);
    conv1x1_kernel<<<784, 256>>>(x, dsq, inv4, bias4, idq);

    dim3 grid(7, 14, NN);   // 16w x 8h tiles
    conv3x3_hmma0<<<grid, 256, SMEM0>>>(xhi, xmid, xlo, bfh, A + 0*CC, B + 0*CC, act1);
    conv3x3_hint<1><<<grid, 256, SMEM0>>>(act1, bfh + 1*9216, A + 1*CC, B + 1*CC, cs + 1*CC, idq,  act2);
    conv3x3_hint<0><<<grid, 256, SMEM0>>>(act2, bfh + 2*9216, A + 2*CC, B + 2*CC, cs + 2*CC, nullptr, act3);
    conv3x3_hint<3><<<grid, 256, SMEM0>>>(act3, bfh + 3*9216, A + 3*CC, B + 3*CC, cs + 3*CC, act2, act4);
    out_expand_kernel<<<16*196, 256>>>(act4, out);
}

// round 16
// speedup vs baseline: 1.3998x; 1.1480x over previous
#include <cuda_runtime.h>
#include <cuda_fp16.h>

#define NN 16
#define CC 64
#define HH 112
#define WW 112
#define HWHW (HH*WW)               // 12544
#define PKW (NN*16*HWHW)           // u8-packed NHWC act words
#define XHW (NN*HWHW*32)           // f16-packed x words (hi/mid/lo)

#define R_S  (10.0f/255.0f)
#define HT_S (10.0f/127.0f)
#define SC_M (1.0f/2048.0f)        // 2^-11
#define SC_L (1.0f/4194304.0f)     // 2^-22

// correctly-rounded reciprocals of the (float) scales, computed in double
#define R_INV  ((float)(1.0/(double)(10.0f/255.0f)))
#define HT_INV ((float)(1.0/(double)(10.0f/127.0f)))

// -------- device scratch ----------
__device__ unsigned g_act1[PKW];
__device__ unsigned g_act2[PKW];
__device__ unsigned g_act3[PKW];
__device__ unsigned g_act4[PKW];
__device__ unsigned g_idq [PKW];
__device__ unsigned g_xhi [XHW];
__device__ unsigned g_xmid[XHW];
__device__ unsigned g_xlo [XHW];
__device__ __align__(16) uint2 g_bfi[3*9*2*8*32];   // int-stage B fragments
__device__ __align__(16) uint2 g_bfh[9*4*8*32];     // stage0 f16 B fragments
__device__ float    g_dsq [CC*CC];
__device__ float    g_wsc [4*CC];
__device__ float    g_A   [4*CC];
__device__ float    g_B   [4*CC];
__device__ float    g_bninv4 [CC];
__device__ float    g_bnbias4[CC];

// ================= helpers =================
__device__ __forceinline__ unsigned smem_u32(const void* p) {
    unsigned a;
    asm("{ .reg .u64 t; cvta.to.shared.u64 t, %1; cvt.u32.u64 %0, t; }" : "=r"(a) : "l"(p));
    return a;
}
__device__ __forceinline__ void ldsm_x4(unsigned& r0, unsigned& r1, unsigned& r2,
                                        unsigned& r3, unsigned addr) {
    asm volatile("ldmatrix.sync.aligned.m8n8.x4.shared.b16 {%0,%1,%2,%3}, [%4];"
        : "=r"(r0), "=r"(r1), "=r"(r2), "=r"(r3) : "r"(addr));
}
__device__ __forceinline__ void mma_s8(int* d, unsigned a0, unsigned a1, unsigned a2,
                                       unsigned a3, unsigned b0, unsigned b1) {
    asm volatile("mma.sync.aligned.m16n8k32.row.col.s32.u8.s8.s32 "
        "{%0,%1,%2,%3}, {%4,%5,%6,%7}, {%8,%9}, {%0,%1,%2,%3};"
        : "+r"(d[0]), "+r"(d[1]), "+r"(d[2]), "+r"(d[3])
        : "r"(a0), "r"(a1), "r"(a2), "r"(a3), "r"(b0), "r"(b1));
}
__device__ __forceinline__ void mma_f16(float* d, unsigned a0, unsigned a1, unsigned a2,
                                        unsigned a3, unsigned b0, unsigned b1) {
    asm volatile("mma.sync.aligned.m16n8k16.row.col.f32.f16.f16.f32 "
        "{%0,%1,%2,%3}, {%4,%5,%6,%7}, {%8,%9}, {%0,%1,%2,%3};"
        : "+f"(d[0]), "+f"(d[1]), "+f"(d[2]), "+f"(d[3])
        : "r"(a0), "r"(a1), "r"(a2), "r"(a3), "r"(b0), "r"(b1));
}

// ================= quantizers (Markstein exact div; round-half-even) ========
__device__ __forceinline__ float qdiv(float c, float S, float Rinv) {
    float q0 = c * Rinv;
    float e  = fmaf(-S, q0, c);
    return fmaf(e, Rinv, q0);         // == __fdiv_rn(c, S) for normal inputs
}
__device__ __forceinline__ float qhtanh_f(float x) {
    float c = fminf(fmaxf(x, -10.0f), 10.0f);
    float r = rintf(qdiv(c, HT_S, HT_INV));
    r = fminf(fmaxf(r, -127.0f), 127.0f);
    return r * HT_S;
}
__device__ __forceinline__ unsigned qrelu_code(float x) {
    float c = fminf(fmaxf(x, 0.0f), 10.0f);
    float r = rintf(qdiv(c, R_S, R_INV));
    return (unsigned)(int)fminf(r, 255.0f);
}
__device__ __forceinline__ unsigned long long pack_dup(float v) {
    unsigned long long r;
    asm("mov.b64 %0, {%1, %1};" : "=l"(r) : "f"(v));
    return r;
}
__device__ __forceinline__ unsigned long long fma2(unsigned long long a, unsigned long long b,
                                                   unsigned long long c) {
    unsigned long long d;
    asm("fma.rn.f32x2 %0, %1, %2, %3;" : "=l"(d) : "l"(a), "l"(b), "l"(c));
    return d;
}
__device__ __forceinline__ void unpack2(unsigned long long v, float& lo, float& hi) {
    asm("mov.b64 {%0, %1}, %2;" : "=f"(lo), "=f"(hi) : "l"(v));
}

// ================= prep1: fused weight prep + x transpose (block roles) ======
#define PREP1_GRID 3546
__global__ void prep1_kernel(const float* __restrict__ w, const float* __restrict__ ds_w,
                             const float* __restrict__ x,
                             float* __restrict__ wsc, uint2* __restrict__ bfi,
                             uint2* __restrict__ bfh, float* __restrict__ dsq,
                             unsigned* __restrict__ xhi, unsigned* __restrict__ xmid,
                             unsigned* __restrict__ xlo) {
    int b = blockIdx.x, tid = threadIdx.x;
    __shared__ float red[256];
    __shared__ unsigned short shi[64][66], smd[64][66], slo[64][66];

    if (b < 256) {                              // ---- weight scale (AVE)
        const float* wc = w + b*576;
        float s = 0.f;
        for (int e = tid; e < 576; e += 256) s += fabsf(wc[e]);
        red[tid] = s;
        __syncthreads();
        for (int off = 128; off > 0; off >>= 1) {
            if (tid < off) red[tid] += red[tid+off];
            __syncthreads();
        }
        if (tid == 0) wsc[b] = fmaxf(red[0] * (1.0f/576.0f), 2e-16f);
    } else if (b < 310) {                       // ---- int-stage B fragments
        int idx = (b-256)*256 + tid;
        if (idx < 3*9*2*8*32) {
            int lane = idx & 31;
            int nt   = (idx >> 5) & 7;
            int c    = (idx >> 8) & 1;
            int tap  = (idx >> 9) % 9;
            int s    = idx / 4608;
            int co   = nt*8 + (lane >> 2);
            unsigned b0 = 0, b1 = 0;
            #pragma unroll
            for (int j = 0; j < 4; j++) {
                int ci0 = c*32 + (lane & 3)*4 + j;
                float v0 = w[(((s+1)*64 + co)*64 + ci0)*9 + tap];
                float v1 = w[(((s+1)*64 + co)*64 + ci0 + 16)*9 + tap];
                b0 |= ((v0 >= 0.f) ? 0x01u : 0xFFu) << (8*j);
                b1 |= ((v1 >= 0.f) ? 0x01u : 0xFFu) << (8*j);
            }
            bfi[idx] = make_uint2(b0, b1);
        }
    } else if (b < 346) {                       // ---- stage0 f16 B fragments
        int idx = (b-310)*256 + tid;
        if (idx < 9*4*8*32) {
            int lane = idx & 31;
            int nt   = (idx >> 5) & 7;
            int c    = (idx >> 8) & 3;
            int tap  = idx >> 10;
            int co   = nt*8 + (lane >> 2);
            int ci   = c*16 + (lane & 3)*2;
            unsigned h00 = (w[((0*64+co)*64 + ci  )*9 + tap] >= 0.f) ? 0x3C00u : 0xBC00u;
            unsigned h01 = (w[((0*64+co)*64 + ci+1)*9 + tap] >= 0.f) ? 0x3C00u : 0xBC00u;
            unsigned h10 = (w[((0*64+co)*64 + ci+8)*9 + tap] >= 0.f) ? 0x3C00u : 0xBC00u;
            unsigned h11 = (w[((0*64+co)*64 + ci+9)*9 + tap] >= 0.f) ? 0x3C00u : 0xBC00u;
            bfh[idx] = make_uint2(h00 | (h01 << 16), h10 | (h11 << 16));
        }
    } else if (b < 410) {                       // ---- int8 1x1 quant
        int co = b - 346;
        red[tid] = (tid < 64) ? fabsf(ds_w[co*64 + tid]) : 0.f;
        __syncthreads();
        for (int off = 128; off > 0; off >>= 1) {
            if (tid < off) red[tid] = fmaxf(red[tid], red[tid+off]);
            __syncthreads();
        }
        if (tid < 64) {
            float scale = fmaxf(red[0], 2e-16f) / 127.0f;
            float q = fminf(fmaxf(rintf(__fdiv_rn(ds_w[co*64 + tid], scale)), -127.f), 127.f) * scale;
            dsq[tid*64 + co] = q;
        }
    } else {                                    // ---- transpose x -> hi/mid/lo
        int blk = b - 410;                      // 0..3135
        int n = blk / 196;
        int pix0 = (blk % 196) * 64;
        #pragma unroll
        for (int pass = 0; pass < 16; pass++) {
            int idx = tid + pass*256;
            int c = idx >> 6, p = idx & 63;
            float v = x[((size_t)n*64 + c)*HWHW + pix0 + p];
            __half h = __float2half_rn(v);
            float r1 = v - __half2float(h);
            __half m = __float2half_rn(r1 * 2048.0f);
            float r2 = r1 - __half2float(m) * SC_M;
            __half l = __float2half_rn(r2 * 4194304.0f);
            shi[p][c] = __half_as_ushort(h);
            smd[p][c] = __half_as_ushort(m);
            slo[p][c] = __half_as_ushort(l);
        }
        __syncthreads();
        int px = tid >> 2, part = tid & 3;
        size_t base = ((size_t)n*HWHW + pix0 + px)*32 + part*8;
        #pragma unroll
        for (int i = 0; i < 8; i++) {
            int c = part*16 + i*2;
            xhi [base+i] = (unsigned)shi[px][c] | ((unsigned)shi[px][c+1] << 16);
            xmid[base+i] = (unsigned)smd[px][c] | ((unsigned)smd[px][c+1] << 16);
            xlo [base+i] = (unsigned)slo[px][c] | ((unsigned)slo[px][c+1] << 16);
        }
    }
}

// ================= prep2: BN coefficients =================
__global__ void prep2_kernel(const float* __restrict__ g, const float* __restrict__ b,
                             const float* __restrict__ m, const float* __restrict__ v,
                             const float* __restrict__ wsc,
                             float* __restrict__ A, float* __restrict__ B,
                             float* __restrict__ inv4, float* __restrict__ bias4) {
    int i = threadIdx.x;   // 320
    float iv = g[i] * __fdiv_rn(1.0f, __fsqrt_rn(v[i] + 1e-5f));
    float bias = b[i] - m[i] * iv;
    if (i < 256) {
        int s = i >> 6;
        float a = wsc[i] * iv;
        if (s > 0) a *= R_S;
        A[i] = a;
        B[i] = bias;
    } else {
        inv4[i-256] = iv;
        bias4[i-256] = bias;
    }
}

// -------- 1x1 conv (downsample) + bn4 + qhtanh -> NHWC packed s8 ------
__global__ __launch_bounds__(256, 2)
void conv1x1_kernel(const float* __restrict__ x, const float* __restrict__ wt,
                    const float* __restrict__ bninv, const float* __restrict__ bnbias,
                    unsigned* __restrict__ out) {
    int b  = blockIdx.x;          // 784 = 16 * 49
    int n  = b / 49;
    int p0 = (b - n*49) * 256;
    __shared__ float xs[16][256];
    __shared__ __align__(8) float ws[16][64];
    __shared__ unsigned s_out[256][16];
    int t   = threadIdx.x;
    int pl  = t & 63;
    int cog = t >> 6;
    unsigned long long acc2[4][8];
    #pragma unroll
    for (int j = 0; j < 4; j++)
        #pragma unroll
        for (int k2 = 0; k2 < 8; k2++) acc2[j][k2] = 0ULL;

    const float* xN = x + (size_t)n*CC*HWHW + p0;
    for (int c0 = 0; c0 < CC; c0 += 16) {
        __syncthreads();
        #pragma unroll
        for (int r = 0; r < 16; r++) xs[r][t] = xN[(size_t)(c0+r)*HWHW + t];
        #pragma unroll
        for (int r = 0; r < 4; r++) {
            int e = t + r*256;
            ws[e>>6][e&63] = wt[(c0 + (e>>6))*64 + (e&63)];
        }
        __syncthreads();
        #pragma unroll
        for (int ci = 0; ci < 16; ci++) {
            unsigned long long w2[8];
            #pragma unroll
            for (int k2 = 0; k2 < 8; k2++)
                w2[k2] = *(const unsigned long long*)&ws[ci][cog*16 + 2*k2];
            #pragma unroll
            for (int j = 0; j < 4; j++) {
                unsigned long long xv2 = pack_dup(xs[ci][pl + 64*j]);
                #pragma unroll
                for (int k2 = 0; k2 < 8; k2++)
                    acc2[j][k2] = fma2(xv2, w2[k2], acc2[j][k2]);
            }
        }
    }
    #pragma unroll
    for (int j = 0; j < 4; j++) {
        unsigned words[4] = {0,0,0,0};
        #pragma unroll
        for (int k2 = 0; k2 < 8; k2++) {
            float a0, a1;
            unpack2(acc2[j][k2], a0, a1);
            #pragma unroll
            for (int h = 0; h < 2; h++) {
                int k = 2*k2 + h;
                int co = cog*16 + k;
                float v = fmaf(h ? a1 : a0, bninv[co], bnbias[co]);
                float c = fminf(fmaxf(v, -10.0f), 10.0f);
                float r = fminf(fmaxf(rintf(qdiv(c, HT_S, HT_INV)), -127.f), 127.f);
                words[k>>2] |= (((unsigned)(int)r) & 0xFFu) << (8*(k&3));
            }
        }
        #pragma unroll
        for (int q = 0; q < 4; q++) s_out[pl + 64*j][cog*4 + q] = words[q];
    }
    __syncthreads();
    uint4* gdst = (uint4*)(out + ((size_t)n*HWHW + p0 + t)*16);
    const uint4* srow = (const uint4*)&s_out[t][0];
    #pragma unroll
    for (int q = 0; q < 4; q++) gdst[q] = srow[q];
}

// ================ HMMA stage 0 (256 thr, 8x16 tile, 3 streamed passes) ========
#define HPITCH_H 36
__global__ __launch_bounds__(256, 2)
void conv3x3_hmma0(const unsigned* __restrict__ xhi, const unsigned* __restrict__ xmid,
                   const unsigned* __restrict__ xlo,
                   const uint2* __restrict__ bfrag,
                   const float* __restrict__ Acoef, const float* __restrict__ Bcoef,
                   unsigned* __restrict__ outp) {
    extern __shared__ char dsm[];
    uint2* sBf = (uint2*)dsm;
    unsigned* halo = (unsigned*)(dsm + 73728);
    __shared__ float sAc[64], sBc[64];

    int tid = threadIdx.x;
    int wid = tid >> 5;
    int lane = tid & 31;
    int n  = blockIdx.z;
    int h0 = blockIdx.y * 8;
    int w0 = blockIdx.x * 16;

    if (tid < 64) { sAc[tid] = Acoef[tid]; sBc[tid] = Bcoef[tid]; }
    {
        const uint4* src = (const uint4*)bfrag;
        uint4* dst = (uint4*)sBf;
        #pragma unroll
        for (int i = 0; i < 18; i++) dst[tid + i*256] = src[tid + i*256];
    }
    unsigned haloAddr = smem_u32(halo);
    unsigned aBase = haloAddr + (unsigned)((wid*18 + (lane & 15))*144 + (lane >> 4)*16);

    float acc[8][4];
    #pragma unroll
    for (int nt = 0; nt < 8; nt++)
        #pragma unroll
        for (int q = 0; q < 4; q++) acc[nt][q] = 0.f;

    #pragma unroll 1
    for (int pass = 0; pass < 3; pass++) {
        const unsigned* xsrc = (pass == 0) ? xlo : (pass == 1) ? xmid : xhi;
        __syncthreads();
        for (int e = tid; e < 5760; e += 256) {
            int r = e / 576, rr = e % 576, c = rr >> 5, q = rr & 31;
            int hh = h0 - 1 + r, ww = w0 - 1 + c;
            unsigned v = 0;
            if ((unsigned)hh < HH && (unsigned)ww < WW)
                v = xsrc[((size_t)n*HWHW + (size_t)hh*WW + ww)*32 + q];
            halo[(r*18 + c)*HPITCH_H + q] = v;
        }
        __syncthreads();
        #pragma unroll 1
        for (int dy = 0; dy < 3; dy++)
        #pragma unroll
        for (int dx = 0; dx < 3; dx++) {
            unsigned rowOff = aBase + (unsigned)((dy*18 + dx)*144);
            #pragma unroll
            for (int c = 0; c < 4; c++) {
                unsigned a0, a1, a2, a3;
                ldsm_x4(a0, a1, a2, a3, rowOff + c*32);
                const uint2* bp = sBf + ((dy*3 + dx)*4 + c)*256 + lane;
                #pragma unroll
                for (int nt = 0; nt < 8; nt++) {
                    uint2 b = bp[nt*32];
                    mma_f16(acc[nt], a0, a1, a2, a3, b.x, b.y);
                }
            }
        }
        if (pass < 2) {
            #pragma unroll
            for (int nt = 0; nt < 8; nt++)
                #pragma unroll
                for (int q = 0; q < 4; q++) acc[nt][q] *= SC_M;
        }
    }

    unsigned short pairs[2][8];
    #pragma unroll
    for (int h2 = 0; h2 < 2; h2++) {
        int px = (lane >> 2) + 8*h2;
        size_t gw = ((size_t)n*HWHW + (size_t)(h0 + wid)*WW + (w0 + px))*32 + (lane & 3);
        #pragma unroll
        for (int nt = 0; nt < 8; nt++) {
            unsigned wh = __ldg(xhi  + gw + nt*4);
            unsigned wm = __ldg(xmid + gw + nt*4);
            unsigned wl = __ldg(xlo  + gw + nt*4);
            unsigned pr = 0;
            #pragma unroll
            for (int j = 0; j < 2; j++) {
                int co = nt*8 + (lane & 3)*2 + j;
                float v = fmaf(acc[nt][2*h2 + j], sAc[co], sBc[co]);
                __half xh = __ushort_as_half((unsigned short)((wh >> (16*j)) & 0xFFFF));
                __half xm = __ushort_as_half((unsigned short)((wm >> (16*j)) & 0xFFFF));
                __half xl = __ushort_as_half((unsigned short)((wl >> (16*j)) & 0xFFFF));
                float xv = (__half2float(xh) + __half2float(xm) * SC_M)
                         + __half2float(xl) * SC_L;
                float r = qhtanh_f(v) + qhtanh_f(xv);
                pr |= qrelu_code(r) << (8*j);
            }
            pairs[h2][nt] = (unsigned short)pr;
        }
    }
    __syncthreads();
    unsigned short* stag = (unsigned short*)halo;
    #pragma unroll
    for (int h2 = 0; h2 < 2; h2++) {
        int px = (lane >> 2) + 8*h2;
        int pxl = wid*16 + px;
        #pragma unroll
        for (int nt = 0; nt < 8; nt++)
            stag[pxl*32 + nt*4 + (lane & 3)] = pairs[h2][nt];
    }
    __syncthreads();
    {
        int pxl = tid >> 1, half = tid & 1;
        int h = h0 + (pxl >> 4), w = w0 + (pxl & 15);
        const uint4* src = (const uint4*)((char*)halo + pxl*64 + half*32);
        uint4* dst = (uint4*)(outp + ((size_t)n*HWHW + (size_t)h*WW + w)*16 + half*8);
        dst[0] = src[0];
        dst[1] = src[1];
    }
}

// ================ IMMA int stages (EPI 0/1/3), 256 thr, 8x16 tile ============
// launch_bounds(256,2) -> 128-reg budget, no spills; smem 51264 still allows 2 CTAs.
#define HPITCH_I 20
template<int EPI>
__global__ __launch_bounds__(256, 2)
void conv3x3_imma(const unsigned* __restrict__ act_in, const uint2* __restrict__ bfrag,
                  const float* __restrict__ Acoef, const float* __restrict__ Bcoef,
                  const unsigned* __restrict__ e1, unsigned* __restrict__ outp) {
    extern __shared__ char dsm[];
    uint2* sBf = (uint2*)dsm;
    unsigned* halo = (unsigned*)(dsm + 36864);
    __shared__ float sAc[64], sBc[64];

    int tid = threadIdx.x;
    int wid = tid >> 5;
    int lane = tid & 31;
    int n  = blockIdx.z;
    int h0 = blockIdx.y * 8;
    int w0 = blockIdx.x * 16;

    if (tid < 64) { sAc[tid] = Acoef[tid]; sBc[tid] = Bcoef[tid]; }
    {
        const uint4* src = (const uint4*)bfrag;
        uint4* dst = (uint4*)sBf;
        #pragma unroll
        for (int i = 0; i < 9; i++) dst[tid + i*256] = src[tid + i*256];
    }
    const unsigned* inN = act_in + (size_t)n*HWHW*16;
    for (int e = tid; e < 2880; e += 256) {
        int r = e / 288, rr = e % 288, c = rr >> 4, q = rr & 15;
        int hh = h0 - 1 + r, ww = w0 - 1 + c;
        unsigned v = 0;
        if ((unsigned)hh < HH && (unsigned)ww < WW)
            v = inN[((size_t)hh*WW + ww)*16 + q];
        halo[(r*18 + c)*HPITCH_I + q] = v;
    }
    __syncthreads();

    unsigned haloAddr = smem_u32(halo);
    unsigned aBase = haloAddr + (unsigned)((wid*18 + (lane & 15))*80 + (lane >> 4)*16);

    int acc[8][4];
    #pragma unroll
    for (int nt = 0; nt < 8; nt++)
        #pragma unroll
        for (int q = 0; q < 4; q++) acc[nt][q] = 0;

    #pragma unroll 1
    for (int dy = 0; dy < 3; dy++)
    #pragma unroll
    for (int dx = 0; dx < 3; dx++) {
        unsigned rowOff = aBase + (unsigned)((dy*18 + dx)*80);
        #pragma unroll
        for (int c = 0; c < 2; c++) {
            unsigned a0, a1, a2, a3;
            ldsm_x4(a0, a1, a2, a3, rowOff + c*32);
            const uint2* bp = sBf + ((dy*3 + dx)*2 + c)*256 + lane;
            #pragma unroll
            for (int nt = 0; nt < 8; nt++) {
                uint2 b = bp[nt*32];
                mma_s8(acc[nt], a0, a1, a2, a3, b.x, b.y);
            }
        }
    }

    // epilogue -> u8 code pairs
    unsigned short pairs[2][8];
    int ctr_row = (wid + 1)*18;
    #pragma unroll
    for (int h2 = 0; h2 < 2; h2++) {
        int px = (lane >> 2) + 8*h2;
        int ctr = (ctr_row + px + 1)*HPITCH_I;
        size_t pixw = ((size_t)n*HWHW + (size_t)(h0 + wid)*WW + (w0 + px))*16;
        int wsel = (lane & 3) >> 1;
        int b0 = ((lane & 3) & 1)*2;
        #pragma unroll
        for (int nt = 0; nt < 8; nt++) {
            unsigned inw = halo[ctr + 2*nt + wsel];
            unsigned ew = 0;
            if (EPI == 1 || EPI == 3) ew = e1[pixw + 2*nt + wsel];
            unsigned pr = 0;
            #pragma unroll
            for (int j = 0; j < 2; j++) {
                int co = nt*8 + (lane & 3)*2 + j;
                float v = fmaf((float)acc[nt][2*h2 + j], sAc[co], sBc[co]);
                int byte = b0 + j;
                float in_val = (float)((inw >> (8*byte)) & 255u) * R_S;
                float r;
                if (EPI == 0) {
                    r = qhtanh_f(v) + qhtanh_f(in_val);
                } else if (EPI == 1) {
                    int ec = (int)(ew << (24 - 8*byte)) >> 24;
                    float tq = qhtanh_f(v) + (float)ec * HT_S;
                    r = qhtanh_f(tq) + qhtanh_f(in_val);
                } else {
                    float ev = (float)((ew >> (8*byte)) & 255u) * R_S;
                    float tq = qhtanh_f(v) + qhtanh_f(ev);
                    r = qhtanh_f(in_val) + qhtanh_f(tq);
                }
                pr |= qrelu_code(r) << (8*j);
            }
            pairs[h2][nt] = (unsigned short)pr;
        }
    }
    __syncthreads();                       // all halo reads done; reuse as staging
    unsigned short* stag = (unsigned short*)halo;
    #pragma unroll
    for (int h2 = 0; h2 < 2; h2++) {
        int px = (lane >> 2) + 8*h2;
        int pxl = wid*16 + px;
        #pragma unroll
        for (int nt = 0; nt < 8; nt++)
            stag[pxl*32 + nt*4 + (lane & 3)] = pairs[h2][nt];
    }
    __syncthreads();
    {
        int pxl = tid >> 1, half = tid & 1;
        int h = h0 + (pxl >> 4), w = w0 + (pxl & 15);
        const uint4* src = (const uint4*)((char*)halo + pxl*64 + half*32);
        uint4* dst = (uint4*)(outp + ((size_t)n*HWHW + (size_t)h*WW + w)*16 + half*8);
        dst[0] = src[0];
        dst[1] = src[1];
    }
}

// -------- final: u8 NHWC codes -> fp32 NCHW (out = code * R_S) --------
__global__ void out_expand_kernel(const unsigned* __restrict__ codes,
                                  float* __restrict__ out) {
    __shared__ unsigned st[64][17];
    int blk = blockIdx.x;             // 16*196
    int n = blk / 196;
    int pix0 = (blk % 196) * 64;
    int tid = threadIdx.x;
    #pragma unroll
    for (int i = 0; i < 4; i++) {
        int e = tid + i*256;
        int px = e >> 4, q = e & 15;
        st[px][q] = codes[((size_t)n*HWHW + pix0 + px)*16 + q];
    }
    __syncthreads();
    int c = tid >> 2, qq = tid & 3;
    float* dst = out + ((size_t)n*64 + c)*HWHW + pix0 + qq*16;
    #pragma unroll
    for (int i = 0; i < 16; i++) {
        unsigned w = st[qq*16 + i][c >> 2];
        dst[i] = (float)((w >> (8*(c & 3))) & 255u) * R_S;
    }
}

// -------------------- host launcher --------------------------------
extern "C" void kernel_launch(void* const* d_in, const int* in_sizes, int n_in,
                              void* d_out, int out_size) {
    const float* x      = (const float*)d_in[0];
    const float* conv_w = (const float*)d_in[1];
    const float* ds_w   = (const float*)d_in[2];
    const float* bng    = (const float*)d_in[3];
    const float* bnb    = (const float*)d_in[4];
    const float* bnm    = (const float*)d_in[5];
    const float* bnvv   = (const float*)d_in[6];
    float* out = (float*)d_out;

    unsigned *act1, *act2, *act3, *act4, *idq, *xhi, *xmid, *xlo;
    uint2 *bfi, *bfh;
    float *dsq, *wsc, *A, *B, *inv4, *bias4;
    cudaGetSymbolAddress((void**)&act1, g_act1);
    cudaGetSymbolAddress((void**)&act2, g_act2);
    cudaGetSymbolAddress((void**)&act3, g_act3);
    cudaGetSymbolAddress((void**)&act4, g_act4);
    cudaGetSymbolAddress((void**)&idq,  g_idq);
    cudaGetSymbolAddress((void**)&xhi,  g_xhi);
    cudaGetSymbolAddress((void**)&xmid, g_xmid);
    cudaGetSymbolAddress((void**)&xlo,  g_xlo);
    cudaGetSymbolAddress((void**)&bfi,  g_bfi);
    cudaGetSymbolAddress((void**)&bfh,  g_bfh);
    cudaGetSymbolAddress((void**)&dsq,  g_dsq);
    cudaGetSymbolAddress((void**)&wsc,  g_wsc);
    cudaGetSymbolAddress((void**)&A,    g_A);
    cudaGetSymbolAddress((void**)&B,    g_B);
    cudaGetSymbolAddress((void**)&inv4, g_bninv4);
    cudaGetSymbolAddress((void**)&bias4,g_bnbias4);

    const int SMEMI = 36864 + 14400;            // 51,264
    const int SMEM0 = 73728 + 25920;            // 99,648 -> 2 CTAs/SM
    cudaFuncSetAttribute(conv3x3_hmma0,   cudaFuncAttributeMaxDynamicSharedMemorySize, SMEM0);
    cudaFuncSetAttribute(conv3x3_imma<0>, cudaFuncAttributeMaxDynamicSharedMemorySize, SMEMI);
    cudaFuncSetAttribute(conv3x3_imma<1>, cudaFuncAttributeMaxDynamicSharedMemorySize, SMEMI);
    cudaFuncSetAttribute(conv3x3_imma<3>, cudaFuncAttributeMaxDynamicSharedMemorySize, SMEMI);

    prep1_kernel<<<PREP1_GRID, 256>>>(conv_w, ds_w, x, wsc, bfi, bfh, dsq, xhi, xmid, xlo);
    prep2_kernel<<<1, 320>>>(bng, bnb, bnm, bnvv, wsc, A, B, inv4, bias4);
    conv1x1_kernel<<<784, 256>>>(x, dsq, inv4, bias4, idq);

    dim3 grid(7, 14, NN);   // 16w x 8h tiles
    conv3x3_hmma0<<<grid, 256, SMEM0>>>(xhi, xmid, xlo, bfh, A + 0*CC, B + 0*CC, act1);
    conv3x3_imma<1><<<grid, 256, SMEMI>>>(act1, bfi + 0*4608, A + 1*CC, B + 1*CC, idq,  act2);
    conv3x3_imma<0><<<grid, 256, SMEMI>>>(act2, bfi + 1*4608, A + 2*CC, B + 2*CC, nullptr, act3);
    conv3x3_imma<3><<<grid, 256, SMEMI>>>(act3, bfi + 2*4608, A + 3*CC, B + 3*CC, act2, act4);
    out_expand_kernel<<<16*196, 256>>>(act4, out);
}

// round 17
// speedup vs baseline: 1.5036x; 1.0741x over previous
#include <cuda_runtime.h>
#include <cuda_fp16.h>

#define NN 16
#define CC 64
#define HH 112
#define WW 112
#define HWHW (HH*WW)               // 12544
#define PKW (NN*16*HWHW)           // u8-packed NHWC act words
#define XHW (NN*HWHW*32)           // f16-packed x words (hi/mid/lo)

#define R_S  (10.0f/255.0f)
#define HT_S (10.0f/127.0f)
#define SC_M (1.0f/2048.0f)        // 2^-11
#define SC_L (1.0f/4194304.0f)     // 2^-22

// correctly-rounded reciprocals of the (float) scales
#define R_INV  ((float)(1.0/(double)(10.0f/255.0f)))
#define HT_INV ((float)(1.0/(double)(10.0f/127.0f)))

// -------- device scratch ----------
__device__ unsigned g_act1[PKW];
__device__ unsigned g_act2[PKW];
__device__ unsigned g_act3[PKW];
__device__ unsigned g_act4[PKW];
__device__ unsigned g_idq [PKW];
__device__ unsigned g_xhi [XHW];
__device__ unsigned g_xmid[XHW];
__device__ unsigned g_xlo [XHW];
__device__ __align__(16) uint2 g_bfi[3*9*2*8*32];   // int-stage B fragments
__device__ __align__(16) uint2 g_bfh[9*4*8*32];     // stage0 f16 B fragments
__device__ float    g_dsq [CC*CC];
__device__ float    g_wsc [4*CC];
__device__ float    g_A   [4*CC];
__device__ float    g_B   [4*CC];
__device__ float    g_bninv4 [CC];
__device__ float    g_bnbias4[CC];

// ================= helpers =================
__device__ __forceinline__ unsigned smem_u32(const void* p) {
    unsigned a;
    asm("{ .reg .u64 t; cvta.to.shared.u64 t, %1; cvt.u32.u64 %0, t; }" : "=r"(a) : "l"(p));
    return a;
}
__device__ __forceinline__ void ldsm_x4(unsigned& r0, unsigned& r1, unsigned& r2,
                                        unsigned& r3, unsigned addr) {
    asm volatile("ldmatrix.sync.aligned.m8n8.x4.shared.b16 {%0,%1,%2,%3}, [%4];"
        : "=r"(r0), "=r"(r1), "=r"(r2), "=r"(r3) : "r"(addr));
}
__device__ __forceinline__ void mma_s8(int* d, unsigned a0, unsigned a1, unsigned a2,
                                       unsigned a3, unsigned b0, unsigned b1) {
    asm volatile("mma.sync.aligned.m16n8k32.row.col.s32.u8.s8.s32 "
        "{%0,%1,%2,%3}, {%4,%5,%6,%7}, {%8,%9}, {%0,%1,%2,%3};"
        : "+r"(d[0]), "+r"(d[1]), "+r"(d[2]), "+r"(d[3])
        : "r"(a0), "r"(a1), "r"(a2), "r"(a3), "r"(b0), "r"(b1));
}
__device__ __forceinline__ void mma_f16(float* d, unsigned a0, unsigned a1, unsigned a2,
                                        unsigned a3, unsigned b0, unsigned b1) {
    asm volatile("mma.sync.aligned.m16n8k16.row.col.f32.f16.f16.f32 "
        "{%0,%1,%2,%3}, {%4,%5,%6,%7}, {%8,%9}, {%0,%1,%2,%3};"
        : "+f"(d[0]), "+f"(d[1]), "+f"(d[2]), "+f"(d[3])
        : "r"(a0), "r"(a1), "r"(a2), "r"(a3), "r"(b0), "r"(b1));
}

// ================= quantizers (Markstein exact div; round-half-even) ========
__device__ __forceinline__ float qdiv(float c, float S, float Rinv) {
    float q0 = c * Rinv;
    float e  = fmaf(-S, q0, c);
    return fmaf(e, Rinv, q0);         // == __fdiv_rn(c, S) for normal inputs
}
__device__ __forceinline__ int qhtanh_int(float x) {
    float c = fminf(fmaxf(x, -10.0f), 10.0f);
    float r = rintf(qdiv(c, HT_S, HT_INV));
    return (int)fminf(fmaxf(r, -127.0f), 127.0f);
}
__device__ __forceinline__ unsigned qrelu_code(float x) {
    float c = fminf(fmaxf(x, 0.0f), 10.0f);
    float r = rintf(qdiv(c, R_S, R_INV));
    return (unsigned)(int)fminf(r, 255.0f);
}
__device__ __forceinline__ unsigned long long pack_dup(float v) {
    unsigned long long r;
    asm("mov.b64 %0, {%1, %1};" : "=l"(r) : "f"(v));
    return r;
}
__device__ __forceinline__ unsigned long long fma2(unsigned long long a, unsigned long long b,
                                                   unsigned long long c) {
    unsigned long long d;
    asm("fma.rn.f32x2 %0, %1, %2, %3;" : "=l"(d) : "l"(a), "l"(b), "l"(c));
    return d;
}
__device__ __forceinline__ void unpack2(unsigned long long v, float& lo, float& hi) {
    asm("mov.b64 {%0, %1}, %2;" : "=f"(lo), "=f"(hi) : "l"(v));
}

// LUT builders (per-CTA smem). s_kht[c] = qhtanh code of u8 relu code c.
// s_lutq[k+254] = qrelu code of k*HT_S (valid: sum of two qhtanh codes).
__device__ __forceinline__ void build_luts(unsigned char* s_kht, unsigned char* s_lutq,
                                           int tid, int nthr) {
    for (int e = tid; e < 256; e += nthr)
        s_kht[e] = (unsigned char)qhtanh_int((float)e * R_S);
    for (int e = tid; e < 509; e += nthr)
        s_lutq[e] = (unsigned char)qrelu_code((float)(e - 254) * HT_S);
}

// ================= prep1: fused weight prep + x transpose (block roles) ======
#define PREP1_GRID 3546
__global__ void prep1_kernel(const float* __restrict__ w, const float* __restrict__ ds_w,
                             const float* __restrict__ x,
                             float* __restrict__ wsc, uint2* __restrict__ bfi,
                             uint2* __restrict__ bfh, float* __restrict__ dsq,
                             unsigned* __restrict__ xhi, unsigned* __restrict__ xmid,
                             unsigned* __restrict__ xlo) {
    int b = blockIdx.x, tid = threadIdx.x;
    __shared__ float red[256];
    __shared__ unsigned short shi[64][66], smd[64][66], slo[64][66];

    if (b < 256) {                              // ---- weight scale (AVE)
        const float* wc = w + b*576;
        float s = 0.f;
        for (int e = tid; e < 576; e += 256) s += fabsf(wc[e]);
        red[tid] = s;
        __syncthreads();
        for (int off = 128; off > 0; off >>= 1) {
            if (tid < off) red[tid] += red[tid+off];
            __syncthreads();
        }
        if (tid == 0) wsc[b] = fmaxf(red[0] * (1.0f/576.0f), 2e-16f);
    } else if (b < 310) {                       // ---- int-stage B fragments
        int idx = (b-256)*256 + tid;
        if (idx < 3*9*2*8*32) {
            int lane = idx & 31;
            int nt   = (idx >> 5) & 7;
            int c    = (idx >> 8) & 1;
            int tap  = (idx >> 9) % 9;
            int s    = idx / 4608;
            int co   = nt*8 + (lane >> 2);
            unsigned b0 = 0, b1 = 0;
            #pragma unroll
            for (int j = 0; j < 4; j++) {
                int ci0 = c*32 + (lane & 3)*4 + j;
                float v0 = w[(((s+1)*64 + co)*64 + ci0)*9 + tap];
                float v1 = w[(((s+1)*64 + co)*64 + ci0 + 16)*9 + tap];
                b0 |= ((v0 >= 0.f) ? 0x01u : 0xFFu) << (8*j);
                b1 |= ((v1 >= 0.f) ? 0x01u : 0xFFu) << (8*j);
            }
            bfi[idx] = make_uint2(b0, b1);
        }
    } else if (b < 346) {                       // ---- stage0 f16 B fragments
        int idx = (b-310)*256 + tid;
        if (idx < 9*4*8*32) {
            int lane = idx & 31;
            int nt   = (idx >> 5) & 7;
            int c    = (idx >> 8) & 3;
            int tap  = idx >> 10;
            int co   = nt*8 + (lane >> 2);
            int ci   = c*16 + (lane & 3)*2;
            unsigned h00 = (w[((0*64+co)*64 + ci  )*9 + tap] >= 0.f) ? 0x3C00u : 0xBC00u;
            unsigned h01 = (w[((0*64+co)*64 + ci+1)*9 + tap] >= 0.f) ? 0x3C00u : 0xBC00u;
            unsigned h10 = (w[((0*64+co)*64 + ci+8)*9 + tap] >= 0.f) ? 0x3C00u : 0xBC00u;
            unsigned h11 = (w[((0*64+co)*64 + ci+9)*9 + tap] >= 0.f) ? 0x3C00u : 0xBC00u;
            bfh[idx] = make_uint2(h00 | (h01 << 16), h10 | (h11 << 16));
        }
    } else if (b < 410) {                       // ---- int8 1x1 quant
        int co = b - 346;
        red[tid] = (tid < 64) ? fabsf(ds_w[co*64 + tid]) : 0.f;
        __syncthreads();
        for (int off = 128; off > 0; off >>= 1) {
            if (tid < off) red[tid] = fmaxf(red[tid], red[tid+off]);
            __syncthreads();
        }
        if (tid < 64) {
            float scale = fmaxf(red[0], 2e-16f) / 127.0f;
            float q = fminf(fmaxf(rintf(__fdiv_rn(ds_w[co*64 + tid], scale)), -127.f), 127.f) * scale;
            dsq[tid*64 + co] = q;
        }
    } else {                                    // ---- transpose x -> hi/mid/lo
        int blk = b - 410;                      // 0..3135
        int n = blk / 196;
        int pix0 = (blk % 196) * 64;
        #pragma unroll
        for (int pass = 0; pass < 16; pass++) {
            int idx = tid + pass*256;
            int c = idx >> 6, p = idx & 63;
            float v = x[((size_t)n*64 + c)*HWHW + pix0 + p];
            __half h = __float2half_rn(v);
            float r1 = v - __half2float(h);
            __half m = __float2half_rn(r1 * 2048.0f);
            float r2 = r1 - __half2float(m) * SC_M;
            __half l = __float2half_rn(r2 * 4194304.0f);
            shi[p][c] = __half_as_ushort(h);
            smd[p][c] = __half_as_ushort(m);
            slo[p][c] = __half_as_ushort(l);
        }
        __syncthreads();
        int px = tid >> 2, part = tid & 3;
        size_t base = ((size_t)n*HWHW + pix0 + px)*32 + part*8;
        #pragma unroll
        for (int i = 0; i < 8; i++) {
            int c = part*16 + i*2;
            xhi [base+i] = (unsigned)shi[px][c] | ((unsigned)shi[px][c+1] << 16);
            xmid[base+i] = (unsigned)smd[px][c] | ((unsigned)smd[px][c+1] << 16);
            xlo [base+i] = (unsigned)slo[px][c] | ((unsigned)slo[px][c+1] << 16);
        }
    }
}

// ================= prep2: BN coefficients =================
__global__ void prep2_kernel(const float* __restrict__ g, const float* __restrict__ b,
                             const float* __restrict__ m, const float* __restrict__ v,
                             const float* __restrict__ wsc,
                             float* __restrict__ A, float* __restrict__ B,
                             float* __restrict__ inv4, float* __restrict__ bias4) {
    int i = threadIdx.x;   // 320
    float iv = g[i] * __fdiv_rn(1.0f, __fsqrt_rn(v[i] + 1e-5f));
    float bias = b[i] - m[i] * iv;
    if (i < 256) {
        int s = i >> 6;
        float a = wsc[i] * iv;
        if (s > 0) a *= R_S;
        A[i] = a;
        B[i] = bias;
    } else {
        inv4[i-256] = iv;
        bias4[i-256] = bias;
    }
}

// -------- 1x1 conv (downsample) + bn4 + qhtanh -> NHWC packed s8 ------
__global__ __launch_bounds__(256, 2)
void conv1x1_kernel(const float* __restrict__ x, const float* __restrict__ wt,
                    const float* __restrict__ bninv, const float* __restrict__ bnbias,
                    unsigned* __restrict__ out) {
    int b  = blockIdx.x;          // 784 = 16 * 49
    int n  = b / 49;
    int p0 = (b - n*49) * 256;
    __shared__ float xs[16][256];
    __shared__ __align__(8) float ws[16][64];
    __shared__ unsigned s_out[256][16];
    int t   = threadIdx.x;
    int pl  = t & 63;
    int cog = t >> 6;
    unsigned long long acc2[4][8];
    #pragma unroll
    for (int j = 0; j < 4; j++)
        #pragma unroll
        for (int k2 = 0; k2 < 8; k2++) acc2[j][k2] = 0ULL;

    const float* xN = x + (size_t)n*CC*HWHW + p0;
    for (int c0 = 0; c0 < CC; c0 += 16) {
        __syncthreads();
        #pragma unroll
        for (int r = 0; r < 16; r++) xs[r][t] = xN[(size_t)(c0+r)*HWHW + t];
        #pragma unroll
        for (int r = 0; r < 4; r++) {
            int e = t + r*256;
            ws[e>>6][e&63] = wt[(c0 + (e>>6))*64 + (e&63)];
        }
        __syncthreads();
        #pragma unroll
        for (int ci = 0; ci < 16; ci++) {
            unsigned long long w2[8];
            #pragma unroll
            for (int k2 = 0; k2 < 8; k2++)
                w2[k2] = *(const unsigned long long*)&ws[ci][cog*16 + 2*k2];
            #pragma unroll
            for (int j = 0; j < 4; j++) {
                unsigned long long xv2 = pack_dup(xs[ci][pl + 64*j]);
                #pragma unroll
                for (int k2 = 0; k2 < 8; k2++)
                    acc2[j][k2] = fma2(xv2, w2[k2], acc2[j][k2]);
            }
        }
    }
    #pragma unroll
    for (int j = 0; j < 4; j++) {
        unsigned words[4] = {0,0,0,0};
        #pragma unroll
        for (int k2 = 0; k2 < 8; k2++) {
            float a0, a1;
            unpack2(acc2[j][k2], a0, a1);
            #pragma unroll
            for (int h = 0; h < 2; h++) {
                int k = 2*k2 + h;
                int co = cog*16 + k;
                float v = fmaf(h ? a1 : a0, bninv[co], bnbias[co]);
                int r = qhtanh_int(v);
                words[k>>2] |= (((unsigned)r) & 0xFFu) << (8*(k&3));
            }
        }
        #pragma unroll
        for (int q = 0; q < 4; q++) s_out[pl + 64*j][cog*4 + q] = words[q];
    }
    __syncthreads();
    uint4* gdst = (uint4*)(out + ((size_t)n*HWHW + p0 + t)*16);
    const uint4* srow = (const uint4*)&s_out[t][0];
    #pragma unroll
    for (int q = 0; q < 4; q++) gdst[q] = srow[q];
}

// ================ HMMA stage 0 (256 thr, 8x16 tile, 3 streamed passes) ========
#define HPITCH_H 36
__global__ __launch_bounds__(256, 2)
void conv3x3_hmma0(const unsigned* __restrict__ xhi, const unsigned* __restrict__ xmid,
                   const unsigned* __restrict__ xlo,
                   const uint2* __restrict__ bfrag,
                   const float* __restrict__ Acoef, const float* __restrict__ Bcoef,
                   unsigned* __restrict__ outp) {
    extern __shared__ char dsm[];
    uint2* sBf = (uint2*)dsm;
    unsigned* halo = (unsigned*)(dsm + 73728);
    __shared__ float sAc[64], sBc[64];
    __shared__ unsigned char s_lutq[512];

    int tid = threadIdx.x;
    int wid = tid >> 5;
    int lane = tid & 31;
    int n  = blockIdx.z;
    int h0 = blockIdx.y * 8;
    int w0 = blockIdx.x * 16;

    if (tid < 64) { sAc[tid] = Acoef[tid]; sBc[tid] = Bcoef[tid]; }
    for (int e = tid; e < 509; e += 256)
        s_lutq[e] = (unsigned char)qrelu_code((float)(e - 254) * HT_S);
    {
        const uint4* src = (const uint4*)bfrag;
        uint4* dst = (uint4*)sBf;
        #pragma unroll
        for (int i = 0; i < 18; i++) dst[tid + i*256] = src[tid + i*256];
    }
    unsigned haloAddr = smem_u32(halo);
    unsigned aBase = haloAddr + (unsigned)((wid*18 + (lane & 15))*144 + (lane >> 4)*16);

    float acc[8][4];
    #pragma unroll
    for (int nt = 0; nt < 8; nt++)
        #pragma unroll
        for (int q = 0; q < 4; q++) acc[nt][q] = 0.f;

    #pragma unroll 1
    for (int pass = 0; pass < 3; pass++) {
        const unsigned* xsrc = (pass == 0) ? xlo : (pass == 1) ? xmid : xhi;
        __syncthreads();
        for (int e = tid; e < 5760; e += 256) {
            int r = e / 576, rr = e % 576, c = rr >> 5, q = rr & 31;
            int hh = h0 - 1 + r, ww = w0 - 1 + c;
            unsigned v = 0;
            if ((unsigned)hh < HH && (unsigned)ww < WW)
                v = xsrc[((size_t)n*HWHW + (size_t)hh*WW + ww)*32 + q];
            halo[(r*18 + c)*HPITCH_H + q] = v;
        }
        __syncthreads();
        #pragma unroll 1
        for (int dy = 0; dy < 3; dy++)
        #pragma unroll
        for (int dx = 0; dx < 3; dx++) {
            unsigned rowOff = aBase + (unsigned)((dy*18 + dx)*144);
            #pragma unroll
            for (int c = 0; c < 4; c++) {
                unsigned a0, a1, a2, a3;
                ldsm_x4(a0, a1, a2, a3, rowOff + c*32);
                const uint2* bp = sBf + ((dy*3 + dx)*4 + c)*256 + lane;
                #pragma unroll
                for (int nt = 0; nt < 8; nt++) {
                    uint2 b = bp[nt*32];
                    mma_f16(acc[nt], a0, a1, a2, a3, b.x, b.y);
                }
            }
        }
        if (pass < 2) {
            #pragma unroll
            for (int nt = 0; nt < 8; nt++)
                #pragma unroll
                for (int q = 0; q < 4; q++) acc[nt][q] *= SC_M;
        }
    }

    unsigned short pairs[2][8];
    #pragma unroll
    for (int h2 = 0; h2 < 2; h2++) {
        int px = (lane >> 2) + 8*h2;
        size_t gw = ((size_t)n*HWHW + (size_t)(h0 + wid)*WW + (w0 + px))*32 + (lane & 3);
        #pragma unroll
        for (int nt = 0; nt < 8; nt++) {
            unsigned wh = __ldg(xhi  + gw + nt*4);
            unsigned wm = __ldg(xmid + gw + nt*4);
            unsigned wl = __ldg(xlo  + gw + nt*4);
            unsigned pr = 0;
            #pragma unroll
            for (int j = 0; j < 2; j++) {
                int co = nt*8 + (lane & 3)*2 + j;
                float v = fmaf(acc[nt][2*h2 + j], sAc[co], sBc[co]);
                __half xh = __ushort_as_half((unsigned short)((wh >> (16*j)) & 0xFFFF));
                __half xm = __ushort_as_half((unsigned short)((wm >> (16*j)) & 0xFFFF));
                __half xl = __ushort_as_half((unsigned short)((wl >> (16*j)) & 0xFFFF));
                float xv = (__half2float(xh) + __half2float(xm) * SC_M)
                         + __half2float(xl) * SC_L;
                int kv = qhtanh_int(v);
                int kx = qhtanh_int(xv);
                unsigned code = s_lutq[kv + kx + 254];
                pr |= code << (8*j);
            }
            pairs[h2][nt] = (unsigned short)pr;
        }
    }
    __syncthreads();
    unsigned short* stag = (unsigned short*)halo;
    #pragma unroll
    for (int h2 = 0; h2 < 2; h2++) {
        int px = (lane >> 2) + 8*h2;
        int pxl = wid*16 + px;
        #pragma unroll
        for (int nt = 0; nt < 8; nt++)
            stag[pxl*32 + nt*4 + (lane & 3)] = pairs[h2][nt];
    }
    __syncthreads();
    {
        int pxl = tid >> 1, half = tid & 1;
        int h = h0 + (pxl >> 4), w = w0 + (pxl & 15);
        const uint4* src = (const uint4*)((char*)halo + pxl*64 + half*32);
        uint4* dst = (uint4*)(outp + ((size_t)n*HWHW + (size_t)h*WW + w)*16 + half*8);
        dst[0] = src[0];
        dst[1] = src[1];
    }
}

// ================ IMMA int stages (EPI 0/1/3), integer-LUT epilogue ==========
#define HPITCH_I 20
template<int EPI>
__global__ __launch_bounds__(256, 2)
void conv3x3_imma(const unsigned* __restrict__ act_in, const uint2* __restrict__ bfrag,
                  const float* __restrict__ Acoef, const float* __restrict__ Bcoef,
                  const unsigned* __restrict__ e1, unsigned* __restrict__ outp) {
    extern __shared__ char dsm[];
    uint2* sBf = (uint2*)dsm;
    unsigned* halo = (unsigned*)(dsm + 36864);
    __shared__ float sAc[64], sBc[64];
    __shared__ unsigned char s_kht[256];
    __shared__ unsigned char s_lutq[512];

    int tid = threadIdx.x;
    int wid = tid >> 5;
    int lane = tid & 31;
    int n  = blockIdx.z;
    int h0 = blockIdx.y * 8;
    int w0 = blockIdx.x * 16;

    if (tid < 64) { sAc[tid] = Acoef[tid]; sBc[tid] = Bcoef[tid]; }
    build_luts(s_kht, s_lutq, tid, 256);
    {
        const uint4* src = (const uint4*)bfrag;
        uint4* dst = (uint4*)sBf;
        #pragma unroll
        for (int i = 0; i < 9; i++) dst[tid + i*256] = src[tid + i*256];
    }
    const unsigned* inN = act_in + (size_t)n*HWHW*16;
    for (int e = tid; e < 2880; e += 256) {
        int r = e / 288, rr = e % 288, c = rr >> 4, q = rr & 15;
        int hh = h0 - 1 + r, ww = w0 - 1 + c;
        unsigned v = 0;
        if ((unsigned)hh < HH && (unsigned)ww < WW)
            v = inN[((size_t)hh*WW + ww)*16 + q];
        halo[(r*18 + c)*HPITCH_I + q] = v;
    }
    __syncthreads();

    unsigned haloAddr = smem_u32(halo);
    unsigned aBase = haloAddr + (unsigned)((wid*18 + (lane & 15))*80 + (lane >> 4)*16);

    int acc[8][4];
    #pragma unroll
    for (int nt = 0; nt < 8; nt++)
        #pragma unroll
        for (int q = 0; q < 4; q++) acc[nt][q] = 0;

    #pragma unroll 1
    for (int dy = 0; dy < 3; dy++)
    #pragma unroll
    for (int dx = 0; dx < 3; dx++) {
        unsigned rowOff = aBase + (unsigned)((dy*18 + dx)*80);
        #pragma unroll
        for (int c = 0; c < 2; c++) {
            unsigned a0, a1, a2, a3;
            ldsm_x4(a0, a1, a2, a3, rowOff + c*32);
            const uint2* bp = sBf + ((dy*3 + dx)*2 + c)*256 + lane;
            #pragma unroll
            for (int nt = 0; nt < 8; nt++) {
                uint2 b = bp[nt*32];
                mma_s8(acc[nt], a0, a1, a2, a3, b.x, b.y);
            }
        }
    }

    // integer-LUT epilogue -> u8 code pairs
    unsigned short pairs[2][8];
    int ctr_row = (wid + 1)*18;
    #pragma unroll
    for (int h2 = 0; h2 < 2; h2++) {
        int px = (lane >> 2) + 8*h2;
        int ctr = (ctr_row + px + 1)*HPITCH_I;
        size_t pixw = ((size_t)n*HWHW + (size_t)(h0 + wid)*WW + (w0 + px))*16;
        int wsel = (lane & 3) >> 1;
        int b0 = ((lane & 3) & 1)*2;
        #pragma unroll
        for (int nt = 0; nt < 8; nt++) {
            unsigned inw = halo[ctr + 2*nt + wsel];
            unsigned ew = 0;
            if (EPI == 1 || EPI == 3) ew = e1[pixw + 2*nt + wsel];
            unsigned pr = 0;
            #pragma unroll
            for (int j = 0; j < 2; j++) {
                int co = nt*8 + (lane & 3)*2 + j;
                float v = fmaf((float)acc[nt][2*h2 + j], sAc[co], sBc[co]);
                int byte = b0 + j;
                int kv = qhtanh_int(v);
                int kin = (int)s_kht[(inw >> (8*byte)) & 255u];
                unsigned code;
                if (EPI == 0) {
                    code = s_lutq[kv + kin + 254];
                } else if (EPI == 1) {
                    int ec = (int)(ew << (24 - 8*byte)) >> 24;   // s8 qhtanh code
                    int kt = min(max(kv + ec, -127), 127);
                    code = s_lutq[kt + kin + 254];
                } else {
                    int ke = (int)s_kht[(ew >> (8*byte)) & 255u];
                    int kt = min(max(kv + ke, -127), 127);
                    code = s_lutq[kin + kt + 254];
                }
                pr |= code << (8*j);
            }
            pairs[h2][nt] = (unsigned short)pr;
        }
    }
    __syncthreads();                       // all halo reads done; reuse as staging
    unsigned short* stag = (unsigned short*)halo;
    #pragma unroll
    for (int h2 = 0; h2 < 2; h2++) {
        int px = (lane >> 2) + 8*h2;
        int pxl = wid*16 + px;
        #pragma unroll
        for (int nt = 0; nt < 8; nt++)
            stag[pxl*32 + nt*4 + (lane & 3)] = pairs[h2][nt];
    }
    __syncthreads();
    {
        int pxl = tid >> 1, half = tid & 1;
        int h = h0 + (pxl >> 4), w = w0 + (pxl & 15);
        const uint4* src = (const uint4*)((char*)halo + pxl*64 + half*32);
        uint4* dst = (uint4*)(outp + ((size_t)n*HWHW + (size_t)h*WW + w)*16 + half*8);
        dst[0] = src[0];
        dst[1] = src[1];
    }
}

// -------- final: u8 NHWC codes -> fp32 NCHW (out = code * R_S) --------
__global__ void out_expand_kernel(const unsigned* __restrict__ codes,
                                  float* __restrict__ out) {
    __shared__ unsigned st[64][17];
    int blk = blockIdx.x;             // 16*196
    int n = blk / 196;
    int pix0 = (blk % 196) * 64;
    int tid = threadIdx.x;
    #pragma unroll
    for (int i = 0; i < 4; i++) {
        int e = tid + i*256;
        int px = e >> 4, q = e & 15;
        st[px][q] = codes[((size_t)n*HWHW + pix0 + px)*16 + q];
    }
    __syncthreads();
    int c = tid >> 2, qq = tid & 3;
    float* dst = out + ((size_t)n*64 + c)*HWHW + pix0 + qq*16;
    #pragma unroll
    for (int i = 0; i < 16; i++) {
        unsigned w = st[qq*16 + i][c >> 2];
        dst[i] = (float)((w >> (8*(c & 3))) & 255u) * R_S;
    }
}

// -------------------- host launcher --------------------------------
extern "C" void kernel_launch(void* const* d_in, const int* in_sizes, int n_in,
                              void* d_out, int out_size) {
    const float* x      = (const float*)d_in[0];
    const float* conv_w = (const float*)d_in[1];
    const float* ds_w   = (const float*)d_in[2];
    const float* bng    = (const float*)d_in[3];
    const float* bnb    = (const float*)d_in[4];
    const float* bnm    = (const float*)d_in[5];
    const float* bnvv   = (const float*)d_in[6];
    float* out = (float*)d_out;

    unsigned *act1, *act2, *act3, *act4, *idq, *xhi, *xmid, *xlo;
    uint2 *bfi, *bfh;
    float *dsq, *wsc, *A, *B, *inv4, *bias4;
    cudaGetSymbolAddress((void**)&act1, g_act1);
    cudaGetSymbolAddress((void**)&act2, g_act2);
    cudaGetSymbolAddress((void**)&act3, g_act3);
    cudaGetSymbolAddress((void**)&act4, g_act4);
    cudaGetSymbolAddress((void**)&idq,  g_idq);
    cudaGetSymbolAddress((void**)&xhi,  g_xhi);
    cudaGetSymbolAddress((void**)&xmid, g_xmid);
    cudaGetSymbolAddress((void**)&xlo,  g_xlo);
    cudaGetSymbolAddress((void**)&bfi,  g_bfi);
    cudaGetSymbolAddress((void**)&bfh,  g_bfh);
    cudaGetSymbolAddress((void**)&dsq,  g_dsq);
    cudaGetSymbolAddress((void**)&wsc,  g_wsc);
    cudaGetSymbolAddress((void**)&A,    g_A);
    cudaGetSymbolAddress((void**)&B,    g_B);
    cudaGetSymbolAddress((void**)&inv4, g_bninv4);
    cudaGetSymbolAddress((void**)&bias4,g_bnbias4);

    const int SMEMI = 36864 + 14400;            // 51,264
    const int SMEM0 = 73728 + 25920;            // 99,648 -> 2 CTAs/SM
    cudaFuncSetAttribute(conv3x3_hmma0,   cudaFuncAttributeMaxDynamicSharedMemorySize, SMEM0);
    cudaFuncSetAttribute(conv3x3_imma<0>, cudaFuncAttributeMaxDynamicSharedMemorySize, SMEMI);
    cudaFuncSetAttribute(conv3x3_imma<1>, cudaFuncAttributeMaxDynamicSharedMemorySize, SMEMI);
    cudaFuncSetAttribute(conv3x3_imma<3>, cudaFuncAttributeMaxDynamicSharedMemorySize, SMEMI);

    prep1_kernel<<<PREP1_GRID, 256>>>(conv_w, ds_w, x, wsc, bfi, bfh, dsq, xhi, xmid, xlo);
    prep2_kernel<<<1, 320>>>(bng, bnb, bnm, bnvv, wsc, A, B, inv4, bias4);
    conv1x1_kernel<<<784, 256>>>(x, dsq, inv4, bias4, idq);

    dim3 grid(7, 14, NN);   // 16w x 8h tiles
    conv3x3_hmma0<<<grid, 256, SMEM0>>>(xhi, xmid, xlo, bfh, A + 0*CC, B + 0*CC, act1);
    conv3x3_imma<1><<<grid, 256, SMEMI>>>(act1, bfi + 0*4608, A + 1*CC, B + 1*CC, idq,  act2);
    conv3x3_imma<0><<<grid, 256, SMEMI>>>(act2, bfi + 1*4608, A + 2*CC, B + 2*CC, nullptr, act3);
    conv3x3_imma<3><<<grid, 256, SMEMI>>>(act3, bfi + 2*4608, A + 3*CC, B + 3*CC, act2, act4);
    out_expand_kernel<<<16*196, 256>>>(act4, out);
}